// round 1
// baseline (speedup 1.0000x reference)
#include <cuda_runtime.h>
#include <math.h>

// Problem constants
#define SQ 2048      // sequence length
#define DM 2048      // model dim
#define NH 32        // query heads
#define NKV 8        // kv heads
#define HD 64        // head dim
#define WIN 1024     // sliding window

// Scratch (device globals; no allocations allowed)
__device__ float g_Q[SQ * NH * HD];    // 16 MB
__device__ float g_K[SQ * NKV * HD];   //  4 MB
__device__ float g_V[SQ * NKV * HD];   //  4 MB
__device__ float g_AO[SQ * NH * HD];   // 16 MB

// ---------------------------------------------------------------------------
// Register-blocked SGEMM: C[M,N] = A[M,K] @ B[K,N], row-major.
// BM=BN=128, BK=16, 256 threads, 8x8 per thread.
// Optional fused RoPE epilogue (for Q and K projections): columns are
// (head*64 + d); pairs (2p, 2p+1) rotated by freqs[row][p].
// ---------------------------------------------------------------------------
template <bool ROPE>
__global__ __launch_bounds__(256)
void gemm_kernel(const float* __restrict__ A, const float* __restrict__ B,
                 float* __restrict__ C, int M, int N, int K,
                 const float* __restrict__ fc, const float* __restrict__ fs)
{
    constexpr int BM = 128, BN = 128, BK = 16, TM = 8, TN = 8;
    __shared__ float As[BK][BM + 1];   // +1 pad: conflict-free transposed stores
    __shared__ float Bs[BK][BN];

    const int tid  = threadIdx.x;
    const int tx   = tid & 15;         // 0..15  (column group)
    const int ty   = tid >> 4;         // 0..15  (row group)
    const int brow = blockIdx.y * BM;
    const int bcol = blockIdx.x * BN;

    float acc[TM][TN];
#pragma unroll
    for (int i = 0; i < TM; i++)
#pragma unroll
        for (int j = 0; j < TN; j++) acc[i][j] = 0.f;

    for (int k0 = 0; k0 < K; k0 += BK) {
        // Load A tile (128x16) and B tile (16x128), float4 vectorized.
#pragma unroll
        for (int it = 0; it < 2; it++) {
            int idx = tid + it * 256;            // 0..511
            // A: r = idx/4 (0..127), kc = (idx%4)*4
            int r  = idx >> 2;
            int kc = (idx & 3) << 2;
            float4 a = *(const float4*)(A + (size_t)(brow + r) * K + k0 + kc);
            As[kc + 0][r] = a.x;
            As[kc + 1][r] = a.y;
            As[kc + 2][r] = a.z;
            As[kc + 3][r] = a.w;
            // B: rb = idx/32 (0..15), cb = (idx%32)*4
            int rb = idx >> 5;
            int cb = (idx & 31) << 2;
            *(float4*)(&Bs[rb][cb]) =
                *(const float4*)(B + (size_t)(k0 + rb) * N + bcol + cb);
        }
        __syncthreads();

#pragma unroll
        for (int kk = 0; kk < BK; kk++) {
            float ra[TM];
#pragma unroll
            for (int i = 0; i < TM; i++) ra[i] = As[kk][ty * TM + i];
            float4 b0 = *(const float4*)(&Bs[kk][tx * TN]);
            float4 b1 = *(const float4*)(&Bs[kk][tx * TN + 4]);
            float rb[TN] = {b0.x, b0.y, b0.z, b0.w, b1.x, b1.y, b1.z, b1.w};
#pragma unroll
            for (int i = 0; i < TM; i++)
#pragma unroll
                for (int j = 0; j < TN; j++)
                    acc[i][j] = fmaf(ra[i], rb[j], acc[i][j]);
        }
        __syncthreads();
    }

    // Epilogue (optional fused RoPE), then float4 stores.
#pragma unroll
    for (int i = 0; i < TM; i++) {
        int row = brow + ty * TM + i;
        if (ROPE) {
#pragma unroll
            for (int j = 0; j < TN; j += 2) {
                int col = bcol + tx * TN + j;
                int p   = (col & (HD - 1)) >> 1;        // pair index within head
                float cs = fc[row * (HD / 2) + p];
                float sn = fs[row * (HD / 2) + p];
                float a = acc[i][j], b = acc[i][j + 1];
                acc[i][j]     = a * cs - b * sn;
                acc[i][j + 1] = a * sn + b * cs;
            }
        }
#pragma unroll
        for (int j = 0; j < TN; j += 4) {
            *(float4*)(C + (size_t)row * N + bcol + tx * TN + j) =
                make_float4(acc[i][j], acc[i][j + 1], acc[i][j + 2], acc[i][j + 3]);
        }
    }
}

// ---------------------------------------------------------------------------
// Flash-style sliding-window causal attention.
// Grid: (q_tiles=16, heads=32). Block: 128 threads, 1 query row per thread.
// K/V streamed in 64-key smem tiles; online softmax in chunks of 16 keys.
// ---------------------------------------------------------------------------
__global__ __launch_bounds__(128)
void attn_kernel(const float* __restrict__ Q, const float* __restrict__ Kg,
                 const float* __restrict__ Vg, float* __restrict__ O)
{
    __shared__ float Ks[64][HD];
    __shared__ float Vs[64][HD];

    const int qt  = blockIdx.x;
    const int h   = blockIdx.y;
    const int tid = threadIdx.x;
    const int i   = qt * 128 + tid;          // query row
    const int kvh = h >> 2;                  // H/KV = 4

    // Load q row, pre-scaled by 1/sqrt(HD) = 0.125
    float q[HD];
    const float* qp = Q + (size_t)i * (NH * HD) + h * HD;
#pragma unroll
    for (int d = 0; d < HD; d += 4) {
        float4 t = *(const float4*)(qp + d);
        q[d] = t.x * 0.125f; q[d + 1] = t.y * 0.125f;
        q[d + 2] = t.z * 0.125f; q[d + 3] = t.w * 0.125f;
    }

    float accv[HD];
#pragma unroll
    for (int d = 0; d < HD; d++) accv[d] = 0.f;
    float m = -INFINITY, l = 0.f;

    const int kt0   = max(0, 2 * qt - 16);
    const int ktmax = 2 * qt + 1;

    for (int kt = kt0; kt <= ktmax; kt++) {
        __syncthreads();
        // Cooperative conflict-free tile load: 64 rows x 64 cols (K and V)
#pragma unroll
        for (int it = 0; it < 8; it++) {
            int idx = tid + it * 128;        // 0..1023 float4s
            int r   = idx >> 4;
            int c4  = (idx & 15) << 2;
            size_t g = (size_t)(kt * 64 + r) * (NKV * HD) + kvh * HD + c4;
            *(float4*)(&Ks[r][c4]) = *(const float4*)(Kg + g);
            *(float4*)(&Vs[r][c4]) = *(const float4*)(Vg + g);
        }
        __syncthreads();

        const int jbase = kt * 64;
#pragma unroll
        for (int c = 0; c < 64; c += 16) {
            float sc[16];
            float cmax = -INFINITY;
#pragma unroll
            for (int t = 0; t < 16; t++) {
                int j = jbase + c + t;
                float s;
                if (j <= i && j >= i - WIN) {
                    float dot = 0.f;
#pragma unroll
                    for (int d = 0; d < HD; d += 4) {
                        float4 kk = *(const float4*)(&Ks[c + t][d]);
                        dot = fmaf(q[d], kk.x, dot);
                        dot = fmaf(q[d + 1], kk.y, dot);
                        dot = fmaf(q[d + 2], kk.z, dot);
                        dot = fmaf(q[d + 3], kk.w, dot);
                    }
                    s = dot;
                } else {
                    s = -INFINITY;
                }
                sc[t] = s;
                cmax = fmaxf(cmax, s);
            }
            if (cmax == -INFINITY) continue;     // fully masked chunk
            if (cmax > m) {
                float f = __expf(m - cmax);      // m=-inf -> f=0 (correct)
                l *= f;
#pragma unroll
                for (int d = 0; d < HD; d++) accv[d] *= f;
                m = cmax;
            }
#pragma unroll
            for (int t = 0; t < 16; t++) {
                float p = __expf(sc[t] - m);     // -inf -> 0
                l += p;
#pragma unroll
                for (int d = 0; d < HD; d += 4) {
                    float4 vv = *(const float4*)(&Vs[c + t][d]);
                    accv[d]     = fmaf(p, vv.x, accv[d]);
                    accv[d + 1] = fmaf(p, vv.y, accv[d + 1]);
                    accv[d + 2] = fmaf(p, vv.z, accv[d + 2]);
                    accv[d + 3] = fmaf(p, vv.w, accv[d + 3]);
                }
            }
        }
    }

    const float inv = 1.f / l;
    float* op = O + (size_t)i * (NH * HD) + h * HD;
#pragma unroll
    for (int d = 0; d < HD; d += 4) {
        *(float4*)(op + d) = make_float4(accv[d] * inv, accv[d + 1] * inv,
                                         accv[d + 2] * inv, accv[d + 3] * inv);
    }
}

// ---------------------------------------------------------------------------
extern "C" void kernel_launch(void* const* d_in, const int* in_sizes, int n_in,
                              void* d_out, int out_size)
{
    const float* x  = (const float*)d_in[0];
    const float* wq = (const float*)d_in[1];
    const float* wk = (const float*)d_in[2];
    const float* wv = (const float*)d_in[3];
    const float* wo = (const float*)d_in[4];
    const float* fc = (const float*)d_in[5];
    const float* fs = (const float*)d_in[6];
    float* out = (float*)d_out;

    float *Qp, *Kp, *Vp, *AOp;
    cudaGetSymbolAddress((void**)&Qp,  g_Q);
    cudaGetSymbolAddress((void**)&Kp,  g_K);
    cudaGetSymbolAddress((void**)&Vp,  g_V);
    cudaGetSymbolAddress((void**)&AOp, g_AO);

    // Q = rope(x @ wq): M=2048, N=2048, K=2048
    gemm_kernel<true><<<dim3(DM / 128, SQ / 128), 256>>>(
        x, wq, Qp, SQ, NH * HD, DM, fc, fs);
    // K = rope(x @ wk): N=512
    gemm_kernel<true><<<dim3((NKV * HD) / 128, SQ / 128), 256>>>(
        x, wk, Kp, SQ, NKV * HD, DM, fc, fs);
    // V = x @ wv
    gemm_kernel<false><<<dim3((NKV * HD) / 128, SQ / 128), 256>>>(
        x, wv, Vp, SQ, NKV * HD, DM, nullptr, nullptr);
    // Sliding-window GQA attention
    attn_kernel<<<dim3(SQ / 128, NH), 128>>>(Qp, Kp, Vp, AOp);
    // out = AO @ wo
    gemm_kernel<false><<<dim3(DM / 128, SQ / 128), 256>>>(
        AOp, wo, out, SQ, DM, NH * HD, nullptr, nullptr);
}

// round 3
// speedup vs baseline: 1.4583x; 1.4583x over previous
#include <cuda_runtime.h>
#include <cuda_bf16.h>
#include <math.h>
#include <stdint.h>

#define SQ 2048
#define DM 2048
#define NH 32
#define NKV 8
#define HD 64
#define WIN 1024
#define KVD (NKV*HD)

// ---------------- scratch (device globals) -----------------------------------
__device__ float g_Q [SQ*NH*HD];
__device__ float g_K [SQ*KVD];
__device__ float g_V [SQ*KVD];
__device__ float g_AO[SQ*NH*HD];
__device__ __nv_bfloat16 g_xh [SQ*DM],  g_xl [SQ*DM];
__device__ __nv_bfloat16 g_wqh[DM*DM],  g_wql[DM*DM];    // [N][K]
__device__ __nv_bfloat16 g_wkh[KVD*DM], g_wkl[KVD*DM];
__device__ __nv_bfloat16 g_wvh[KVD*DM], g_wvl[KVD*DM];
__device__ __nv_bfloat16 g_woh[DM*DM],  g_wol[DM*DM];
__device__ __nv_bfloat16 g_aoh[SQ*DM],  g_aol[SQ*DM];

// ---------------- helpers -----------------------------------------------------
__device__ __forceinline__ uint32_t smem_u32(const void* p) {
    uint32_t a;
    asm("{ .reg .u64 t; cvta.to.shared.u64 t, %1; cvt.u32.u64 %0, t; }" : "=r"(a) : "l"(p));
    return a;
}
__device__ __forceinline__ uint32_t sw128(uint32_t o) { return o ^ ((o >> 3) & 0x70); }

__device__ __forceinline__ void ldsm_x4(uint32_t (&r)[4], uint32_t addr) {
    asm volatile("ldmatrix.sync.aligned.m8n8.x4.shared.b16 {%0,%1,%2,%3}, [%4];"
                 : "=r"(r[0]), "=r"(r[1]), "=r"(r[2]), "=r"(r[3]) : "r"(addr));
}
__device__ __forceinline__ void ldsm_x2(uint32_t (&r)[2], uint32_t addr) {
    asm volatile("ldmatrix.sync.aligned.m8n8.x2.shared.b16 {%0,%1}, [%2];"
                 : "=r"(r[0]), "=r"(r[1]) : "r"(addr));
}
__device__ __forceinline__ void mma16816(float* c, const uint32_t (&a)[4], const uint32_t (&b)[2]) {
    asm volatile("mma.sync.aligned.m16n8k16.row.col.f32.bf16.bf16.f32 "
                 "{%0,%1,%2,%3}, {%4,%5,%6,%7}, {%8,%9}, {%0,%1,%2,%3};"
                 : "+f"(c[0]), "+f"(c[1]), "+f"(c[2]), "+f"(c[3])
                 : "r"(a[0]), "r"(a[1]), "r"(a[2]), "r"(a[3]), "r"(b[0]), "r"(b[1]));
}

// ---------------- pre-pass kernels --------------------------------------------
__global__ void split_kernel(const float* __restrict__ X, __nv_bfloat16* __restrict__ H,
                             __nv_bfloat16* __restrict__ L, int n4)
{
    int i = blockIdx.x * blockDim.x + threadIdx.x;
    if (i >= n4) return;
    float4 v = ((const float4*)X)[i];
    __nv_bfloat16 h0 = __float2bfloat16_rn(v.x);
    __nv_bfloat16 h1 = __float2bfloat16_rn(v.y);
    __nv_bfloat16 h2 = __float2bfloat16_rn(v.z);
    __nv_bfloat16 h3 = __float2bfloat16_rn(v.w);
    __nv_bfloat16 l0 = __float2bfloat16_rn(v.x - __bfloat162float(h0));
    __nv_bfloat16 l1 = __float2bfloat16_rn(v.y - __bfloat162float(h1));
    __nv_bfloat16 l2 = __float2bfloat16_rn(v.z - __bfloat162float(h2));
    __nv_bfloat16 l3 = __float2bfloat16_rn(v.w - __bfloat162float(h3));
    __nv_bfloat162* H2 = (__nv_bfloat162*)H;
    __nv_bfloat162* L2 = (__nv_bfloat162*)L;
    H2[2*i]     = __halves2bfloat162(h0, h1);
    H2[2*i + 1] = __halves2bfloat162(h2, h3);
    L2[2*i]     = __halves2bfloat162(l0, l1);
    L2[2*i + 1] = __halves2bfloat162(l2, l3);
}

// W[K][N] fp32 -> Th/Tl[N][K] bf16 (hi/lo split)
__global__ void transpose_split(const float* __restrict__ W, __nv_bfloat16* __restrict__ Th,
                                __nv_bfloat16* __restrict__ Tl, int K, int N)
{
    __shared__ float t[32][33];
    int n0 = blockIdx.x * 32, k0 = blockIdx.y * 32;
    int tx = threadIdx.x, ty = threadIdx.y;
#pragma unroll
    for (int j = ty; j < 32; j += 8)
        t[j][tx] = W[(size_t)(k0 + j) * N + n0 + tx];
    __syncthreads();
#pragma unroll
    for (int j = ty; j < 32; j += 8) {
        float v = t[tx][j];
        __nv_bfloat16 h = __float2bfloat16_rn(v);
        __nv_bfloat16 l = __float2bfloat16_rn(v - __bfloat162float(h));
        size_t o = (size_t)(n0 + j) * K + k0 + tx;
        Th[o] = h; Tl[o] = l;
    }
}

// ---------------- warp-MMA split-bf16 GEMM -------------------------------------
// C[M,N] = A[M,K] @ B^T, A hi/lo row-major [M,K], B hi/lo [N,K].
// Block tile 128x128, BK=64, 8 warps (2m x 4n), warp tile 64x32.
// smem: Ah(16K) Al(16K) Bh(16K) Bl(16K) = 64KB, SW128-swizzled 128B rows.
static constexpr int GEMM_SMEM = 65536;

template <bool ROPE>
__global__ __launch_bounds__(256)
void mma_gemm(const __nv_bfloat16* __restrict__ Ah, const __nv_bfloat16* __restrict__ Al,
              const __nv_bfloat16* __restrict__ Bh, const __nv_bfloat16* __restrict__ Bl,
              float* __restrict__ C, int N, int K,
              const float* __restrict__ fc, const float* __restrict__ fs)
{
    extern __shared__ char sm[];
    const uint32_t sbase = smem_u32(sm);
    const int tid  = threadIdx.x;
    const int warp = tid >> 5;
    const int lane = tid & 31;
    const int wm   = (warp & 1) * 64;     // warp m offset in tile
    const int wn   = (warp >> 1) * 32;    // warp n offset in tile
    const int brow = blockIdx.y * 128;
    const int bcol = blockIdx.x * 128;

    char* sAh = sm;
    char* sAl = sm + 16384;
    char* sBh = sm + 32768;
    char* sBl = sm + 49152;

    float acc[4][4][4];
#pragma unroll
    for (int i = 0; i < 4; i++)
#pragma unroll
        for (int j = 0; j < 4; j++)
#pragma unroll
            for (int e = 0; e < 4; e++) acc[i][j][e] = 0.f;

    // Precompute ldmatrix smem addresses (constant across chunks except kstep)
    // A: row_local = (lane&7) + 8*((lane>>3)&1), khalf byte = 16*(lane>>4)
    const int a_r  = (lane & 7) + 8 * ((lane >> 3) & 1);
    const int a_kb = 16 * (lane >> 4);
    // B: row_local = lane&7 (lanes 0-15), khalf byte = 16*((lane>>3)&1)
    const int b_r  = lane & 7;
    const int b_kb = 16 * ((lane >> 3) & 1);

    const int nch = K >> 6;
    for (int c = 0; c < nch; c++) {
        const int k0 = c << 6;
        // cooperative fill: each array 1024 uint4; 256 threads x 4
#pragma unroll
        for (int it = 0; it < 4; it++) {
            int idx = tid + it * 256;          // 0..1023
            int r   = idx >> 3;                // 0..127
            int cb  = (idx & 7) << 4;          // byte col 0..112
            uint32_t off = sw128((uint32_t)(r * 128 + cb));
            int ke = cb >> 1;                  // element offset in k
            *(uint4*)(sAh + off) = *(const uint4*)(Ah + (size_t)(brow + r) * K + k0 + ke);
            *(uint4*)(sAl + off) = *(const uint4*)(Al + (size_t)(brow + r) * K + k0 + ke);
            *(uint4*)(sBh + off) = *(const uint4*)(Bh + (size_t)(bcol + r) * K + k0 + ke);
            *(uint4*)(sBl + off) = *(const uint4*)(Bl + (size_t)(bcol + r) * K + k0 + ke);
        }
        __syncthreads();

#pragma unroll
        for (int ks = 0; ks < 4; ks++) {
            const int kb = ks * 32;            // byte offset of this k16 step
            uint32_t bh[4][2], bl[4][2];
#pragma unroll
            for (int nt = 0; nt < 4; nt++) {
                uint32_t boff = sw128((uint32_t)((wn + nt * 8 + b_r) * 128 + kb + b_kb));
                ldsm_x2(bh[nt], sbase + 32768 + boff);
                ldsm_x2(bl[nt], sbase + 49152 + boff);
            }
#pragma unroll
            for (int mt = 0; mt < 4; mt++) {
                uint32_t aoff = sw128((uint32_t)((wm + mt * 16 + a_r) * 128 + kb + a_kb));
                uint32_t ah[4], al[4];
                ldsm_x4(ah, sbase + aoff);
                ldsm_x4(al, sbase + 16384 + aoff);
#pragma unroll
                for (int nt = 0; nt < 4; nt++) {
                    mma16816(acc[mt][nt], ah, bh[nt]);
                    mma16816(acc[mt][nt], ah, bl[nt]);
                    mma16816(acc[mt][nt], al, bh[nt]);
                }
            }
        }
        __syncthreads();
    }

    // Epilogue: thread owns (m = 16*mt + lane/4 [+8], n = 8*nt + 2*(lane&3) +{0,1})
    const int mrow0 = brow + wm + (lane >> 2);
    const int ncol0 = bcol + wn + 2 * (lane & 3);
#pragma unroll
    for (int mt = 0; mt < 4; mt++) {
#pragma unroll
        for (int half = 0; half < 2; half++) {
            const int m = mrow0 + mt * 16 + half * 8;
#pragma unroll
            for (int nt = 0; nt < 4; nt++) {
                float v0 = acc[mt][nt][half * 2];
                float v1 = acc[mt][nt][half * 2 + 1];
                const int n = ncol0 + nt * 8;
                if (ROPE) {
                    int p = (n & (HD - 1)) >> 1;
                    float cs = fc[m * (HD / 2) + p];
                    float sn = fs[m * (HD / 2) + p];
                    float a = v0, b = v1;
                    v0 = a * cs - b * sn;
                    v1 = a * sn + b * cs;
                }
                *(float2*)(C + (size_t)m * N + n) = make_float2(v0, v1);
            }
        }
    }
}

// ---------------- attention (fp32 flash, unchanged) ----------------------------
__global__ __launch_bounds__(128)
void attn_kernel(const float* __restrict__ Q, const float* __restrict__ Kg,
                 const float* __restrict__ Vg, float* __restrict__ O)
{
    __shared__ float Ks[64][HD];
    __shared__ float Vs[64][HD];

    const int qt  = blockIdx.x;
    const int h   = blockIdx.y;
    const int tid = threadIdx.x;
    const int i   = qt * 128 + tid;
    const int kvh = h >> 2;

    float q[HD];
    const float* qp = Q + (size_t)i * (NH * HD) + h * HD;
#pragma unroll
    for (int d = 0; d < HD; d += 4) {
        float4 t = *(const float4*)(qp + d);
        q[d] = t.x * 0.125f; q[d + 1] = t.y * 0.125f;
        q[d + 2] = t.z * 0.125f; q[d + 3] = t.w * 0.125f;
    }

    float accv[HD];
#pragma unroll
    for (int d = 0; d < HD; d++) accv[d] = 0.f;
    float m = -INFINITY, l = 0.f;

    const int kt0   = max(0, 2 * qt - 16);
    const int ktmax = 2 * qt + 1;

    for (int kt = kt0; kt <= ktmax; kt++) {
        __syncthreads();
#pragma unroll
        for (int it = 0; it < 8; it++) {
            int idx = tid + it * 128;
            int r   = idx >> 4;
            int c4  = (idx & 15) << 2;
            size_t g = (size_t)(kt * 64 + r) * (NKV * HD) + kvh * HD + c4;
            *(float4*)(&Ks[r][c4]) = *(const float4*)(Kg + g);
            *(float4*)(&Vs[r][c4]) = *(const float4*)(Vg + g);
        }
        __syncthreads();

        const int jbase = kt * 64;
#pragma unroll
        for (int c = 0; c < 64; c += 16) {
            float sc[16];
            float cmax = -INFINITY;
#pragma unroll
            for (int t = 0; t < 16; t++) {
                int j = jbase + c + t;
                float s;
                if (j <= i && j >= i - WIN) {
                    float dot = 0.f;
#pragma unroll
                    for (int d = 0; d < HD; d += 4) {
                        float4 kk = *(const float4*)(&Ks[c + t][d]);
                        dot = fmaf(q[d], kk.x, dot);
                        dot = fmaf(q[d + 1], kk.y, dot);
                        dot = fmaf(q[d + 2], kk.z, dot);
                        dot = fmaf(q[d + 3], kk.w, dot);
                    }
                    s = dot;
                } else {
                    s = -INFINITY;
                }
                sc[t] = s;
                cmax = fmaxf(cmax, s);
            }
            if (cmax == -INFINITY) continue;
            if (cmax > m) {
                float f = __expf(m - cmax);
                l *= f;
#pragma unroll
                for (int d = 0; d < HD; d++) accv[d] *= f;
                m = cmax;
            }
#pragma unroll
            for (int t = 0; t < 16; t++) {
                float p = __expf(sc[t] - m);
                l += p;
#pragma unroll
                for (int d = 0; d < HD; d += 4) {
                    float4 vv = *(const float4*)(&Vs[c + t][d]);
                    accv[d]     = fmaf(p, vv.x, accv[d]);
                    accv[d + 1] = fmaf(p, vv.y, accv[d + 1]);
                    accv[d + 2] = fmaf(p, vv.z, accv[d + 2]);
                    accv[d + 3] = fmaf(p, vv.w, accv[d + 3]);
                }
            }
        }
    }

    const float inv = 1.f / l;
    float* op = O + (size_t)i * (NH * HD) + h * HD;
#pragma unroll
    for (int d = 0; d < HD; d += 4) {
        *(float4*)(op + d) = make_float4(accv[d] * inv, accv[d + 1] * inv,
                                         accv[d + 2] * inv, accv[d + 3] * inv);
    }
}

// ---------------- launch --------------------------------------------------------
extern "C" void kernel_launch(void* const* d_in, const int* in_sizes, int n_in,
                              void* d_out, int out_size)
{
    const float* x  = (const float*)d_in[0];
    const float* wq = (const float*)d_in[1];
    const float* wk = (const float*)d_in[2];
    const float* wv = (const float*)d_in[3];
    const float* wo = (const float*)d_in[4];
    const float* fc = (const float*)d_in[5];
    const float* fs = (const float*)d_in[6];
    float* out = (float*)d_out;

    float *Qp, *Kp, *Vp, *AOp;
    __nv_bfloat16 *xh, *xl, *wqh, *wql, *wkh, *wkl, *wvh, *wvl, *woh, *wol, *aoh, *aol;
    cudaGetSymbolAddress((void**)&Qp,  g_Q);
    cudaGetSymbolAddress((void**)&Kp,  g_K);
    cudaGetSymbolAddress((void**)&Vp,  g_V);
    cudaGetSymbolAddress((void**)&AOp, g_AO);
    cudaGetSymbolAddress((void**)&xh,  g_xh);  cudaGetSymbolAddress((void**)&xl,  g_xl);
    cudaGetSymbolAddress((void**)&wqh, g_wqh); cudaGetSymbolAddress((void**)&wql, g_wql);
    cudaGetSymbolAddress((void**)&wkh, g_wkh); cudaGetSymbolAddress((void**)&wkl, g_wkl);
    cudaGetSymbolAddress((void**)&wvh, g_wvh); cudaGetSymbolAddress((void**)&wvl, g_wvl);
    cudaGetSymbolAddress((void**)&woh, g_woh); cudaGetSymbolAddress((void**)&wol, g_wol);
    cudaGetSymbolAddress((void**)&aoh, g_aoh); cudaGetSymbolAddress((void**)&aol, g_aol);

    cudaFuncSetAttribute(mma_gemm<true>,  cudaFuncAttributeMaxDynamicSharedMemorySize, GEMM_SMEM);
    cudaFuncSetAttribute(mma_gemm<false>, cudaFuncAttributeMaxDynamicSharedMemorySize, GEMM_SMEM);

    const int n4 = SQ * DM / 4;
    split_kernel<<<n4 / 256, 256>>>(x, xh, xl, n4);
    transpose_split<<<dim3(DM / 32,  DM / 32), dim3(32, 8)>>>(wq, wqh, wql, DM, DM);
    transpose_split<<<dim3(KVD / 32, DM / 32), dim3(32, 8)>>>(wk, wkh, wkl, DM, KVD);
    transpose_split<<<dim3(KVD / 32, DM / 32), dim3(32, 8)>>>(wv, wvh, wvl, DM, KVD);
    transpose_split<<<dim3(DM / 32,  DM / 32), dim3(32, 8)>>>(wo, woh, wol, DM, DM);

    mma_gemm<true ><<<dim3(16, 16), 256, GEMM_SMEM>>>(xh, xl, wqh, wql, Qp, DM,  DM, fc, fs);
    mma_gemm<true ><<<dim3( 4, 16), 256, GEMM_SMEM>>>(xh, xl, wkh, wkl, Kp, KVD, DM, fc, fs);
    mma_gemm<false><<<dim3( 4, 16), 256, GEMM_SMEM>>>(xh, xl, wvh, wvl, Vp, KVD, DM, nullptr, nullptr);

    attn_kernel<<<dim3(SQ / 128, NH), 128>>>(Qp, Kp, Vp, AOp);

    split_kernel<<<n4 / 256, 256>>>(AOp, aoh, aol, n4);
    mma_gemm<false><<<dim3(16, 16), 256, GEMM_SMEM>>>(aoh, aol, woh, wol, out, DM, DM, nullptr, nullptr);
}

// round 4
// speedup vs baseline: 4.3017x; 2.9498x over previous
#include <cuda_runtime.h>
#include <cuda_bf16.h>
#include <math.h>
#include <stdint.h>

#define SQ 2048
#define DM 2048
#define NH 32
#define NKV 8
#define HD 64
#define WIN 1024
#define KVD (NKV*HD)

// ---------------- scratch (device globals) -----------------------------------
__device__ __nv_bfloat16 g_xh [SQ*DM],  g_xl [SQ*DM];
__device__ __nv_bfloat16 g_wqh[DM*DM],  g_wql[DM*DM];    // [N][K]
__device__ __nv_bfloat16 g_wkh[KVD*DM], g_wkl[KVD*DM];
__device__ __nv_bfloat16 g_wvh[KVD*DM], g_wvl[KVD*DM];
__device__ __nv_bfloat16 g_woh[DM*DM],  g_wol[DM*DM];
__device__ __nv_bfloat16 g_Qh [SQ*DM],  g_Ql [SQ*DM];    // rope'd, scaled
__device__ __nv_bfloat16 g_Kh [SQ*KVD], g_Kl [SQ*KVD];   // rope'd
__device__ __nv_bfloat16 g_Vh [SQ*KVD], g_Vl [SQ*KVD];
__device__ __nv_bfloat16 g_aoh[SQ*DM],  g_aol[SQ*DM];

// ---------------- helpers -----------------------------------------------------
__device__ __forceinline__ uint32_t smem_u32(const void* p) {
    uint32_t a;
    asm("{ .reg .u64 t; cvta.to.shared.u64 t, %1; cvt.u32.u64 %0, t; }" : "=r"(a) : "l"(p));
    return a;
}
__device__ __forceinline__ uint32_t sw128(uint32_t o) { return o ^ ((o >> 3) & 0x70); }

__device__ __forceinline__ void cp16(uint32_t s, const void* g) {
    asm volatile("cp.async.cg.shared.global [%0], [%1], 16;" :: "r"(s), "l"(g));
}
__device__ __forceinline__ void cp_commit() { asm volatile("cp.async.commit_group;" ::: "memory"); }
template<int N> __device__ __forceinline__ void cp_wait() {
    asm volatile("cp.async.wait_group %0;" :: "n"(N) : "memory");
}

__device__ __forceinline__ void ldsm_x4(uint32_t (&r)[4], uint32_t addr) {
    asm volatile("ldmatrix.sync.aligned.m8n8.x4.shared.b16 {%0,%1,%2,%3}, [%4];"
                 : "=r"(r[0]), "=r"(r[1]), "=r"(r[2]), "=r"(r[3]) : "r"(addr));
}
__device__ __forceinline__ void ldsm_x2(uint32_t (&r)[2], uint32_t addr) {
    asm volatile("ldmatrix.sync.aligned.m8n8.x2.shared.b16 {%0,%1}, [%2];"
                 : "=r"(r[0]), "=r"(r[1]) : "r"(addr));
}
__device__ __forceinline__ void ldsm_x2t(uint32_t (&r)[2], uint32_t addr) {
    asm volatile("ldmatrix.sync.aligned.m8n8.x2.trans.shared.b16 {%0,%1}, [%2];"
                 : "=r"(r[0]), "=r"(r[1]) : "r"(addr));
}
__device__ __forceinline__ void mma16816(float* c, const uint32_t (&a)[4], const uint32_t (&b)[2]) {
    asm volatile("mma.sync.aligned.m16n8k16.row.col.f32.bf16.bf16.f32 "
                 "{%0,%1,%2,%3}, {%4,%5,%6,%7}, {%8,%9}, {%0,%1,%2,%3};"
                 : "+f"(c[0]), "+f"(c[1]), "+f"(c[2]), "+f"(c[3])
                 : "r"(a[0]), "r"(a[1]), "r"(a[2]), "r"(a[3]), "r"(b[0]), "r"(b[1]));
}
__device__ __forceinline__ uint32_t pack_bf16(float lo, float hi) {
    uint32_t r;
    asm("cvt.rn.bf16x2.f32 %0, %1, %2;" : "=r"(r) : "f"(hi), "f"(lo));
    return r;
}
// split (v0,v1) into bf16 hi pair + bf16 residual pair
__device__ __forceinline__ void split2(float v0, float v1, uint32_t& hp, uint32_t& lp) {
    hp = pack_bf16(v0, v1);
    float f0 = __uint_as_float(hp << 16);
    float f1 = __uint_as_float(hp & 0xffff0000u);
    lp = pack_bf16(v0 - f0, v1 - f1);
}

// ---------------- pre-pass kernels --------------------------------------------
__global__ void split_kernel(const float* __restrict__ X, __nv_bfloat16* __restrict__ H,
                             __nv_bfloat16* __restrict__ L, int n4)
{
    int i = blockIdx.x * blockDim.x + threadIdx.x;
    if (i >= n4) return;
    float4 v = ((const float4*)X)[i];
    uint32_t h0, l0, h1, l1;
    split2(v.x, v.y, h0, l0);
    split2(v.z, v.w, h1, l1);
    ((uint32_t*)H)[2*i] = h0; ((uint32_t*)H)[2*i+1] = h1;
    ((uint32_t*)L)[2*i] = l0; ((uint32_t*)L)[2*i+1] = l1;
}

// W[K][N] fp32 -> Th/Tl[N][K] bf16 (hi/lo split)
__global__ void transpose_split(const float* __restrict__ W, __nv_bfloat16* __restrict__ Th,
                                __nv_bfloat16* __restrict__ Tl, int K, int N)
{
    __shared__ float t[32][33];
    int n0 = blockIdx.x * 32, k0 = blockIdx.y * 32;
    int tx = threadIdx.x, ty = threadIdx.y;
#pragma unroll
    for (int j = ty; j < 32; j += 8)
        t[j][tx] = W[(size_t)(k0 + j) * N + n0 + tx];
    __syncthreads();
#pragma unroll
    for (int j = ty; j < 32; j += 8) {
        float v = t[tx][j];
        __nv_bfloat16 h = __float2bfloat16_rn(v);
        __nv_bfloat16 l = __float2bfloat16_rn(v - __bfloat162float(h));
        size_t o = (size_t)(n0 + j) * K + k0 + tx;
        Th[o] = h; Tl[o] = l;
    }
}

// ---------------- warp-MMA split-bf16 GEMM, cp.async 2-stage --------------------
// C = A[M,K] @ B^T ; A hi/lo row-major, B hi/lo [N][K].
// Block tile 128x128, BK=64, 8 warps (2m x 4n), warp tile 64x32.
// MODE: 0 = fp32 out; 1 = rope+0.125+split; 2 = rope+split; 3 = split.
static constexpr int GEMM_SMEM = 2 * 65536;

template <int MODE>
__global__ __launch_bounds__(256)
void mma_gemm(const __nv_bfloat16* __restrict__ Ah, const __nv_bfloat16* __restrict__ Al,
              const __nv_bfloat16* __restrict__ Bh, const __nv_bfloat16* __restrict__ Bl,
              void* __restrict__ C0, __nv_bfloat16* __restrict__ C1, int N, int K,
              const float* __restrict__ fc, const float* __restrict__ fs)
{
    extern __shared__ char sm[];
    const uint32_t sbase = smem_u32(sm);
    const int tid  = threadIdx.x;
    const int warp = tid >> 5;
    const int lane = tid & 31;
    const int wm   = (warp & 1) * 64;
    const int wn   = (warp >> 1) * 32;
    const int brow = blockIdx.y * 128;
    const int bcol = blockIdx.x * 128;

    float acc[4][4][4];
#pragma unroll
    for (int i = 0; i < 4; i++)
#pragma unroll
        for (int j = 0; j < 4; j++)
#pragma unroll
            for (int e = 0; e < 4; e++) acc[i][j][e] = 0.f;

    const int a_r  = (lane & 7) + 8 * ((lane >> 3) & 1);
    const int a_kb = 16 * (lane >> 4);
    const int b_r  = lane & 7;
    const int b_kb = 16 * ((lane >> 3) & 1);

    const int ldr = tid >> 3;            // 0..31? no: tid 0..255 >>3 = 0..31 rows/iter... see loop
    const int ldc = (tid & 7);           // 16B column

    auto load_stage = [&](int s, int k0) {
        uint32_t base = sbase + s * 65536;
#pragma unroll
        for (int it = 0; it < 4; it++) {
            int idx = tid + it * 256;
            int r   = idx >> 3;
            int c   = idx & 7;
            uint32_t off = sw128((uint32_t)(r * 128 + c * 16));
            cp16(base + off,         Ah + (size_t)(brow + r) * K + k0 + c * 8);
            cp16(base + 16384 + off, Al + (size_t)(brow + r) * K + k0 + c * 8);
            cp16(base + 32768 + off, Bh + (size_t)(bcol + r) * K + k0 + c * 8);
            cp16(base + 49152 + off, Bl + (size_t)(bcol + r) * K + k0 + c * 8);
        }
    };

    const int nch = K >> 6;
    load_stage(0, 0);
    cp_commit();

    for (int c = 0; c < nch; c++) {
        const int s = c & 1;
        if (c + 1 < nch) { load_stage(s ^ 1, (c + 1) << 6); cp_commit(); cp_wait<1>(); }
        else             { cp_wait<0>(); }
        __syncthreads();

        uint32_t base = sbase + s * 65536;
#pragma unroll
        for (int ks = 0; ks < 4; ks++) {
            const int kb = ks * 32;
            uint32_t bh[4][2], bl[4][2];
#pragma unroll
            for (int nt = 0; nt < 4; nt++) {
                uint32_t boff = sw128((uint32_t)((wn + nt * 8 + b_r) * 128 + kb + b_kb));
                ldsm_x2(bh[nt], base + 32768 + boff);
                ldsm_x2(bl[nt], base + 49152 + boff);
            }
#pragma unroll
            for (int mt = 0; mt < 4; mt++) {
                uint32_t aoff = sw128((uint32_t)((wm + mt * 16 + a_r) * 128 + kb + a_kb));
                uint32_t ah[4], al[4];
                ldsm_x4(ah, base + aoff);
                ldsm_x4(al, base + 16384 + aoff);
#pragma unroll
                for (int nt = 0; nt < 4; nt++) {
                    mma16816(acc[mt][nt], ah, bh[nt]);
                    mma16816(acc[mt][nt], ah, bl[nt]);
                    mma16816(acc[mt][nt], al, bh[nt]);
                }
            }
        }
        __syncthreads();
    }

    (void)ldr; (void)ldc;
    const int mrow0 = brow + wm + (lane >> 2);
    const int ncol0 = bcol + wn + 2 * (lane & 3);
#pragma unroll
    for (int mt = 0; mt < 4; mt++) {
#pragma unroll
        for (int half = 0; half < 2; half++) {
            const int m = mrow0 + mt * 16 + half * 8;
#pragma unroll
            for (int nt = 0; nt < 4; nt++) {
                float v0 = acc[mt][nt][half * 2];
                float v1 = acc[mt][nt][half * 2 + 1];
                const int n = ncol0 + nt * 8;
                if (MODE == 1 || MODE == 2) {
                    int p = (n & (HD - 1)) >> 1;
                    float cs = fc[m * (HD / 2) + p];
                    float sn = fs[m * (HD / 2) + p];
                    float a = v0, b = v1;
                    v0 = a * cs - b * sn;
                    v1 = a * sn + b * cs;
                    if (MODE == 1) { v0 *= 0.125f; v1 *= 0.125f; }
                }
                if (MODE == 0) {
                    *(float2*)((float*)C0 + (size_t)m * N + n) = make_float2(v0, v1);
                } else {
                    uint32_t hp, lp;
                    split2(v0, v1, hp, lp);
                    *(uint32_t*)((__nv_bfloat16*)C0 + (size_t)m * N + n) = hp;
                    *(uint32_t*)(C1 + (size_t)m * N + n) = lp;
                }
            }
        }
    }
}

// ---------------- MMA flash attention -----------------------------------------
// Block: 128 thr (4 warps), 64 queries (16/warp), 64-key tiles, 2-stage cp.async.
// smem: Q hi/lo 16KB + 2 stages x (Kh,Kl,Vh,Vl 8KB each) = 81920 B.
static constexpr int ATTN_SMEM = 16384 + 2 * 32768;

__global__ __launch_bounds__(128)
void attn_mma(const __nv_bfloat16* __restrict__ Qh, const __nv_bfloat16* __restrict__ Ql,
              const __nv_bfloat16* __restrict__ Kh, const __nv_bfloat16* __restrict__ Kl,
              const __nv_bfloat16* __restrict__ Vh, const __nv_bfloat16* __restrict__ Vl,
              __nv_bfloat16* __restrict__ Oh, __nv_bfloat16* __restrict__ Ol)
{
    extern __shared__ char sm[];
    const uint32_t sb = smem_u32(sm);
    const int tid  = threadIdx.x;
    const int warp = tid >> 5;
    const int lane = tid & 31;
    const int qt   = blockIdx.x;
    const int h    = blockIdx.y;
    const int kvh  = h >> 2;
    const int qb   = qt * 64;

    const uint32_t sQh = sb, sQl = sb + 8192;
    const uint32_t st0 = sb + 16384;

    // ---- prologue: load Q tile + first KV tile
    const int kt0 = max(0, (qb - WIN) >> 6);
#pragma unroll
    for (int it = 0; it < 4; it++) {
        int idx = tid + it * 128;
        int r = idx >> 3, c = idx & 7;
        uint32_t off = sw128((uint32_t)(r * 128 + c * 16));
        size_t go = (size_t)(qb + r) * DM + h * HD + c * 8;
        cp16(sQh + off, Qh + go);
        cp16(sQl + off, Ql + go);
    }
    auto load_kv = [&](uint32_t base, int kt) {
#pragma unroll
        for (int it = 0; it < 4; it++) {
            int idx = tid + it * 128;
            int r = idx >> 3, c = idx & 7;
            uint32_t off = sw128((uint32_t)(r * 128 + c * 16));
            size_t go = (size_t)(kt * 64 + r) * KVD + kvh * HD + c * 8;
            cp16(base + off,         Kh + go);
            cp16(base + 8192 + off,  Kl + go);
            cp16(base + 16384 + off, Vh + go);
            cp16(base + 24576 + off, Vl + go);
        }
    };
    load_kv(st0, kt0);
    cp_commit();
    cp_wait<0>();
    __syncthreads();

    // ---- Q fragments (A layout), resident in registers
    uint32_t qfh[4][4], qfl[4][4];
    {
        const int a_r  = warp * 16 + (lane & 7) + 8 * ((lane >> 3) & 1);
        const int a_kb = 16 * (lane >> 4);
#pragma unroll
        for (int ks = 0; ks < 4; ks++) {
            uint32_t off = sw128((uint32_t)(a_r * 128 + ks * 32 + a_kb));
            ldsm_x4(qfh[ks], sQh + off);
            ldsm_x4(qfl[ks], sQl + off);
        }
    }

    float O[8][4];
#pragma unroll
    for (int nt = 0; nt < 8; nt++)
#pragma unroll
        for (int e = 0; e < 4; e++) O[nt][e] = 0.f;
    float m0 = -1e20f, m1 = -1e20f, l0 = 0.f, l1 = 0.f;

    const int i0 = qb + warp * 16 + (lane >> 2);
    const int i1 = i0 + 8;
    const int jc = 2 * (lane & 3);
    const int b_r  = lane & 7;
    const int b_kb = 16 * ((lane >> 3) & 1);
    const int v_r  = lane & 15;

    for (int kt = kt0; kt <= qt; kt++) {
        const int buf = (kt - kt0) & 1;
        if (kt < qt) { load_kv(st0 + (buf ^ 1) * 32768, kt + 1); cp_commit(); cp_wait<1>(); }
        else         { cp_wait<0>(); }
        __syncthreads();

        const uint32_t bK_h = st0 + buf * 32768;
        const uint32_t bK_l = bK_h + 8192;
        const uint32_t bV_h = bK_h + 16384;
        const uint32_t bV_l = bK_h + 24576;

        // ---- scores S = Q @ K^T (3-term split)
        float S[8][4];
#pragma unroll
        for (int nt = 0; nt < 8; nt++) {
#pragma unroll
            for (int e = 0; e < 4; e++) S[nt][e] = 0.f;
#pragma unroll
            for (int ks = 0; ks < 4; ks++) {
                uint32_t boff = sw128((uint32_t)((nt * 8 + b_r) * 128 + ks * 32 + b_kb));
                uint32_t bh[2], bl[2];
                ldsm_x2(bh, bK_h + boff);
                ldsm_x2(bl, bK_l + boff);
                mma16816(S[nt], qfh[ks], bh);
                mma16816(S[nt], qfl[ks], bh);
                mma16816(S[nt], qfh[ks], bl);
            }
        }

        // ---- mask (only first/diag tiles are partial)
        const int ktb = kt * 64;
        const bool full = (ktb >= qb + 64 - WIN) && (kt < qt);
        if (!full) {
#pragma unroll
            for (int nt = 0; nt < 8; nt++) {
                int j = ktb + nt * 8 + jc;
                if (j > i0 || j < i0 - WIN)         S[nt][0] = -1e30f;
                if (j + 1 > i0 || j + 1 < i0 - WIN) S[nt][1] = -1e30f;
                if (j > i1 || j < i1 - WIN)         S[nt][2] = -1e30f;
                if (j + 1 > i1 || j + 1 < i1 - WIN) S[nt][3] = -1e30f;
            }
        }

        // ---- online softmax
        float mx0 = -1e30f, mx1 = -1e30f;
#pragma unroll
        for (int nt = 0; nt < 8; nt++) {
            mx0 = fmaxf(mx0, fmaxf(S[nt][0], S[nt][1]));
            mx1 = fmaxf(mx1, fmaxf(S[nt][2], S[nt][3]));
        }
        mx0 = fmaxf(mx0, __shfl_xor_sync(0xffffffffu, mx0, 1));
        mx0 = fmaxf(mx0, __shfl_xor_sync(0xffffffffu, mx0, 2));
        mx1 = fmaxf(mx1, __shfl_xor_sync(0xffffffffu, mx1, 1));
        mx1 = fmaxf(mx1, __shfl_xor_sync(0xffffffffu, mx1, 2));
        const float mn0 = fmaxf(m0, mx0);
        const float mn1 = fmaxf(m1, mx1);
        const float sc0 = exp2f((m0 - mn0) * 1.44269504f);
        const float sc1 = exp2f((m1 - mn1) * 1.44269504f);
        m0 = mn0; m1 = mn1;
        l0 *= sc0; l1 *= sc1;
        float rs0 = 0.f, rs1 = 0.f;
#pragma unroll
        for (int nt = 0; nt < 8; nt++) {
            S[nt][0] = exp2f((S[nt][0] - mn0) * 1.44269504f);
            S[nt][1] = exp2f((S[nt][1] - mn0) * 1.44269504f);
            S[nt][2] = exp2f((S[nt][2] - mn1) * 1.44269504f);
            S[nt][3] = exp2f((S[nt][3] - mn1) * 1.44269504f);
            rs0 += S[nt][0] + S[nt][1];
            rs1 += S[nt][2] + S[nt][3];
            O[nt][0] *= sc0; O[nt][1] *= sc0;
            O[nt][2] *= sc1; O[nt][3] *= sc1;
        }
        rs0 += __shfl_xor_sync(0xffffffffu, rs0, 1);
        rs0 += __shfl_xor_sync(0xffffffffu, rs0, 2);
        rs1 += __shfl_xor_sync(0xffffffffu, rs1, 1);
        rs1 += __shfl_xor_sync(0xffffffffu, rs1, 2);
        l0 += rs0; l1 += rs1;

        // ---- pack P into A fragments (hi/lo)
        uint32_t pah[4][4], pal[4][4];
#pragma unroll
        for (int ks = 0; ks < 4; ks++) {
            split2(S[2*ks][0],   S[2*ks][1],   pah[ks][0], pal[ks][0]);
            split2(S[2*ks][2],   S[2*ks][3],   pah[ks][1], pal[ks][1]);
            split2(S[2*ks+1][0], S[2*ks+1][1], pah[ks][2], pal[ks][2]);
            split2(S[2*ks+1][2], S[2*ks+1][3], pah[ks][3], pal[ks][3]);
        }

        // ---- O += P @ V (3-term split), V^T fragments via ldmatrix.trans
#pragma unroll
        for (int nt = 0; nt < 8; nt++) {
#pragma unroll
            for (int ks = 0; ks < 4; ks++) {
                uint32_t voff = sw128((uint32_t)((ks * 16 + v_r) * 128 + nt * 16));
                uint32_t vh[2], vl[2];
                ldsm_x2t(vh, bV_h + voff);
                ldsm_x2t(vl, bV_l + voff);
                mma16816(O[nt], pah[ks], vh);
                mma16816(O[nt], pah[ks], vl);
                mma16816(O[nt], pal[ks], vh);
            }
        }
        __syncthreads();
    }

    // ---- epilogue: normalize, split to bf16 hi/lo, store
    const float inv0 = 1.f / l0;
    const float inv1 = 1.f / l1;
    const int row0 = qb + warp * 16 + (lane >> 2);
    const int colb = h * HD + jc;
#pragma unroll
    for (int nt = 0; nt < 8; nt++) {
        uint32_t hp, lp;
        split2(O[nt][0] * inv0, O[nt][1] * inv0, hp, lp);
        size_t o = (size_t)row0 * DM + colb + nt * 8;
        *(uint32_t*)(Oh + o) = hp;
        *(uint32_t*)(Ol + o) = lp;
        split2(O[nt][2] * inv1, O[nt][3] * inv1, hp, lp);
        o += (size_t)8 * DM;
        *(uint32_t*)(Oh + o) = hp;
        *(uint32_t*)(Ol + o) = lp;
    }
}

// ---------------- launch --------------------------------------------------------
extern "C" void kernel_launch(void* const* d_in, const int* in_sizes, int n_in,
                              void* d_out, int out_size)
{
    const float* x  = (const float*)d_in[0];
    const float* wq = (const float*)d_in[1];
    const float* wk = (const float*)d_in[2];
    const float* wv = (const float*)d_in[3];
    const float* wo = (const float*)d_in[4];
    const float* fc = (const float*)d_in[5];
    const float* fs = (const float*)d_in[6];
    float* out = (float*)d_out;

    __nv_bfloat16 *xh, *xl, *wqh, *wql, *wkh, *wkl, *wvh, *wvl, *woh, *wol;
    __nv_bfloat16 *qh, *ql, *kh, *kl, *vh, *vl, *aoh, *aol;
    cudaGetSymbolAddress((void**)&xh,  g_xh);  cudaGetSymbolAddress((void**)&xl,  g_xl);
    cudaGetSymbolAddress((void**)&wqh, g_wqh); cudaGetSymbolAddress((void**)&wql, g_wql);
    cudaGetSymbolAddress((void**)&wkh, g_wkh); cudaGetSymbolAddress((void**)&wkl, g_wkl);
    cudaGetSymbolAddress((void**)&wvh, g_wvh); cudaGetSymbolAddress((void**)&wvl, g_wvl);
    cudaGetSymbolAddress((void**)&woh, g_woh); cudaGetSymbolAddress((void**)&wol, g_wol);
    cudaGetSymbolAddress((void**)&qh,  g_Qh);  cudaGetSymbolAddress((void**)&ql,  g_Ql);
    cudaGetSymbolAddress((void**)&kh,  g_Kh);  cudaGetSymbolAddress((void**)&kl,  g_Kl);
    cudaGetSymbolAddress((void**)&vh,  g_Vh);  cudaGetSymbolAddress((void**)&vl,  g_Vl);
    cudaGetSymbolAddress((void**)&aoh, g_aoh); cudaGetSymbolAddress((void**)&aol, g_aol);

    cudaFuncSetAttribute(mma_gemm<0>, cudaFuncAttributeMaxDynamicSharedMemorySize, GEMM_SMEM);
    cudaFuncSetAttribute(mma_gemm<1>, cudaFuncAttributeMaxDynamicSharedMemorySize, GEMM_SMEM);
    cudaFuncSetAttribute(mma_gemm<2>, cudaFuncAttributeMaxDynamicSharedMemorySize, GEMM_SMEM);
    cudaFuncSetAttribute(mma_gemm<3>, cudaFuncAttributeMaxDynamicSharedMemorySize, GEMM_SMEM);
    cudaFuncSetAttribute(attn_mma,    cudaFuncAttributeMaxDynamicSharedMemorySize, ATTN_SMEM);

    const int n4 = SQ * DM / 4;
    split_kernel<<<n4 / 256, 256>>>(x, xh, xl, n4);
    transpose_split<<<dim3(DM / 32,  DM / 32), dim3(32, 8)>>>(wq, wqh, wql, DM, DM);
    transpose_split<<<dim3(KVD / 32, DM / 32), dim3(32, 8)>>>(wk, wkh, wkl, DM, KVD);
    transpose_split<<<dim3(KVD / 32, DM / 32), dim3(32, 8)>>>(wv, wvh, wvl, DM, KVD);
    transpose_split<<<dim3(DM / 32,  DM / 32), dim3(32, 8)>>>(wo, woh, wol, DM, DM);

    mma_gemm<1><<<dim3(16, 16), 256, GEMM_SMEM>>>(xh, xl, wqh, wql, qh, ql, DM,  DM, fc, fs);
    mma_gemm<2><<<dim3( 4, 16), 256, GEMM_SMEM>>>(xh, xl, wkh, wkl, kh, kl, KVD, DM, fc, fs);
    mma_gemm<3><<<dim3( 4, 16), 256, GEMM_SMEM>>>(xh, xl, wvh, wvl, vh, vl, KVD, DM, nullptr, nullptr);

    attn_mma<<<dim3(SQ / 64, NH), 128, ATTN_SMEM>>>(qh, ql, kh, kl, vh, vl, aoh, aol);

    mma_gemm<0><<<dim3(16, 16), 256, GEMM_SMEM>>>(aoh, aol, woh, wol, out, nullptr, DM, DM, nullptr, nullptr);
}

// round 5
// speedup vs baseline: 4.7297x; 1.0995x over previous
#include <cuda_runtime.h>
#include <cuda_bf16.h>
#include <math.h>
#include <stdint.h>

#define SQ 2048
#define DM 2048
#define NH 32
#define NKV 8
#define HD 64
#define WIN 1024
#define KVD (NKV*HD)

// ---------------- scratch (device globals) -----------------------------------
__device__ __nv_bfloat16 g_xh [SQ*DM],  g_xl [SQ*DM];
__device__ __nv_bfloat16 g_wqh[DM*DM],  g_wql[DM*DM];    // [N][K]
__device__ __nv_bfloat16 g_wkh[KVD*DM], g_wkl[KVD*DM];
__device__ __nv_bfloat16 g_wvh[KVD*DM], g_wvl[KVD*DM];
__device__ __nv_bfloat16 g_woh[DM*DM],  g_wol[DM*DM];
__device__ __nv_bfloat16 g_Qh [SQ*DM],  g_Ql [SQ*DM];    // rope'd, scaled
__device__ __nv_bfloat16 g_Kh [SQ*KVD], g_Kl [SQ*KVD];   // rope'd
__device__ __nv_bfloat16 g_Vh [SQ*KVD], g_Vl [SQ*KVD];
__device__ __nv_bfloat16 g_aoh[SQ*DM],  g_aol[SQ*DM];

// ---------------- helpers -----------------------------------------------------
__device__ __forceinline__ uint32_t smem_u32(const void* p) {
    uint32_t a;
    asm("{ .reg .u64 t; cvta.to.shared.u64 t, %1; cvt.u32.u64 %0, t; }" : "=r"(a) : "l"(p));
    return a;
}
__device__ __forceinline__ uint32_t sw128(uint32_t o) { return o ^ ((o >> 3) & 0x70); }

__device__ __forceinline__ void cp16(uint32_t s, const void* g) {
    asm volatile("cp.async.cg.shared.global [%0], [%1], 16;" :: "r"(s), "l"(g));
}
__device__ __forceinline__ void cp_commit() { asm volatile("cp.async.commit_group;" ::: "memory"); }
template<int N> __device__ __forceinline__ void cp_wait() {
    asm volatile("cp.async.wait_group %0;" :: "n"(N) : "memory");
}

__device__ __forceinline__ void ldsm_x4(uint32_t (&r)[4], uint32_t addr) {
    asm volatile("ldmatrix.sync.aligned.m8n8.x4.shared.b16 {%0,%1,%2,%3}, [%4];"
                 : "=r"(r[0]), "=r"(r[1]), "=r"(r[2]), "=r"(r[3]) : "r"(addr));
}
__device__ __forceinline__ void ldsm_x2(uint32_t (&r)[2], uint32_t addr) {
    asm volatile("ldmatrix.sync.aligned.m8n8.x2.shared.b16 {%0,%1}, [%2];"
                 : "=r"(r[0]), "=r"(r[1]) : "r"(addr));
}
__device__ __forceinline__ void ldsm_x2t(uint32_t (&r)[2], uint32_t addr) {
    asm volatile("ldmatrix.sync.aligned.m8n8.x2.trans.shared.b16 {%0,%1}, [%2];"
                 : "=r"(r[0]), "=r"(r[1]) : "r"(addr));
}
__device__ __forceinline__ void mma16816(float* c, const uint32_t (&a)[4], const uint32_t (&b)[2]) {
    asm volatile("mma.sync.aligned.m16n8k16.row.col.f32.bf16.bf16.f32 "
                 "{%0,%1,%2,%3}, {%4,%5,%6,%7}, {%8,%9}, {%0,%1,%2,%3};"
                 : "+f"(c[0]), "+f"(c[1]), "+f"(c[2]), "+f"(c[3])
                 : "r"(a[0]), "r"(a[1]), "r"(a[2]), "r"(a[3]), "r"(b[0]), "r"(b[1]));
}
__device__ __forceinline__ uint32_t pack_bf16(float lo, float hi) {
    uint32_t r;
    asm("cvt.rn.bf16x2.f32 %0, %1, %2;" : "=r"(r) : "f"(hi), "f"(lo));
    return r;
}
__device__ __forceinline__ void split2(float v0, float v1, uint32_t& hp, uint32_t& lp) {
    hp = pack_bf16(v0, v1);
    float f0 = __uint_as_float(hp << 16);
    float f1 = __uint_as_float(hp & 0xffff0000u);
    lp = pack_bf16(v0 - f0, v1 - f1);
}

// ---------------- pre-pass: split x ------------------------------------------
__global__ void split_kernel(const float* __restrict__ X, __nv_bfloat16* __restrict__ H,
                             __nv_bfloat16* __restrict__ L, int n4)
{
    int i = blockIdx.x * blockDim.x + threadIdx.x;
    if (i >= n4) return;
    float4 v = ((const float4*)X)[i];
    uint32_t h0, l0, h1, l1;
    split2(v.x, v.y, h0, l0);
    split2(v.z, v.w, h1, l1);
    ((uint32_t*)H)[2*i] = h0; ((uint32_t*)H)[2*i+1] = h1;
    ((uint32_t*)L)[2*i] = l0; ((uint32_t*)L)[2*i+1] = l1;
}

// ---------------- pre-pass: all-weight transpose+split, one launch -------------
// Tile: 64 k-rows x 32 n-cols. Output rows n, contiguous k, uint32 stores.
__device__ __forceinline__ void tsplit_tile(const float* __restrict__ W,
                                            __nv_bfloat16* __restrict__ Th,
                                            __nv_bfloat16* __restrict__ Tl,
                                            int K, int N, int tile, float (*t)[33])
{
    const int tid = threadIdx.x;
    const int ntn = N >> 5;
    const int k0 = (tile / ntn) << 6;
    const int n0 = (tile % ntn) << 5;
#pragma unroll
    for (int it = 0; it < 8; it++) {
        int idx = tid + it * 256;          // 0..2047
        int r = idx >> 5, c = idx & 31;
        t[r][c] = W[(size_t)(k0 + r) * N + n0 + c];
    }
    __syncthreads();
    const int n  = tid >> 3;
    const int kk = tid & 7;
#pragma unroll
    for (int it = 0; it < 4; it++) {
        int kp = kk + it * 8;              // pair index 0..31
        uint32_t hp, lp;
        split2(t[2*kp][n], t[2*kp+1][n], hp, lp);
        size_t o = (size_t)(n0 + n) * K + k0 + 2 * kp;
        *(uint32_t*)(Th + o) = hp;
        *(uint32_t*)(Tl + o) = lp;
    }
    __syncthreads();
}

__global__ __launch_bounds__(256)
void transpose_split_all(const float* __restrict__ wq, const float* __restrict__ wk,
                         const float* __restrict__ wv, const float* __restrict__ wo,
                         __nv_bfloat16* wqh, __nv_bfloat16* wql,
                         __nv_bfloat16* wkh, __nv_bfloat16* wkl,
                         __nv_bfloat16* wvh, __nv_bfloat16* wvl,
                         __nv_bfloat16* woh, __nv_bfloat16* wol)
{
    __shared__ float t[64][33];
    int b = blockIdx.x;                    // 0..5119
    if (b < 2048)        tsplit_tile(wq, wqh, wql, DM, DM,  b,        t);
    else if (b < 2560)   tsplit_tile(wk, wkh, wkl, DM, KVD, b - 2048, t);
    else if (b < 3072)   tsplit_tile(wv, wvh, wvl, DM, KVD, b - 2560, t);
    else                 tsplit_tile(wo, woh, wol, DM, DM,  b - 3072, t);
}

// ---------------- GEMM core: 3-stage cp.async, 128x128 tile, BK=64 -------------
static constexpr int GEMM_SMEM = 3 * 65536;

struct GemmAcc { float a[4][4][4]; };

__device__ __forceinline__ void gemm_mainloop(
    const __nv_bfloat16* __restrict__ Ah, const __nv_bfloat16* __restrict__ Al,
    const __nv_bfloat16* __restrict__ Bh, const __nv_bfloat16* __restrict__ Bl,
    int brow, int bcol, int K, uint32_t sbase, char* /*unused*/, GemmAcc& acc)
{
    const int tid  = threadIdx.x;
    const int warp = tid >> 5;
    const int lane = tid & 31;
    const int wm   = (warp & 1) * 64;
    const int wn   = (warp >> 1) * 32;

    const int a_r  = (lane & 7) + 8 * ((lane >> 3) & 1);
    const int a_kb = 16 * (lane >> 4);
    const int b_r  = lane & 7;
    const int b_kb = 16 * ((lane >> 3) & 1);

    auto load_stage = [&](int s, int k0) {
        uint32_t base = sbase + s * 65536;
#pragma unroll
        for (int it = 0; it < 4; it++) {
            int idx = tid + it * 256;
            int r   = idx >> 3;
            int c   = idx & 7;
            uint32_t off = sw128((uint32_t)(r * 128 + c * 16));
            cp16(base + off,         Ah + (size_t)(brow + r) * K + k0 + c * 8);
            cp16(base + 16384 + off, Al + (size_t)(brow + r) * K + k0 + c * 8);
            cp16(base + 32768 + off, Bh + (size_t)(bcol + r) * K + k0 + c * 8);
            cp16(base + 49152 + off, Bl + (size_t)(bcol + r) * K + k0 + c * 8);
        }
    };

    const int nch = K >> 6;
    load_stage(0, 0);  cp_commit();
    load_stage(1, 64); cp_commit();

    int s = 0;
    for (int c = 0; c < nch; c++) {
        if (c + 2 < nch) load_stage((s + 2 >= 3) ? s - 1 : s + 2, (c + 2) << 6);
        cp_commit();                        // possibly empty group (tail)
        cp_wait<2>();
        __syncthreads();

        uint32_t base = sbase + s * 65536;
#pragma unroll
        for (int ks = 0; ks < 4; ks++) {
            const int kb = ks * 32;
            uint32_t bh[4][2], bl[4][2];
#pragma unroll
            for (int nt = 0; nt < 4; nt++) {
                uint32_t boff = sw128((uint32_t)((wn + nt * 8 + b_r) * 128 + kb + b_kb));
                ldsm_x2(bh[nt], base + 32768 + boff);
                ldsm_x2(bl[nt], base + 49152 + boff);
            }
#pragma unroll
            for (int mt = 0; mt < 4; mt++) {
                uint32_t aoff = sw128((uint32_t)((wm + mt * 16 + a_r) * 128 + kb + a_kb));
                uint32_t ah[4], al[4];
                ldsm_x4(ah, base + aoff);
                ldsm_x4(al, base + 16384 + aoff);
#pragma unroll
                for (int nt = 0; nt < 4; nt++) {
                    mma16816(acc.a[mt][nt], ah, bh[nt]);
                    mma16816(acc.a[mt][nt], ah, bl[nt]);
                    mma16816(acc.a[mt][nt], al, bh[nt]);
                }
            }
        }
        __syncthreads();
        s = (s + 1 >= 3) ? 0 : s + 1;
    }
}

// Fused QKV projection: grid.x = 24 (0-15 Q | 16-19 K | 20-23 V), grid.y = 16.
__global__ __launch_bounds__(256)
void qkv_gemm(const __nv_bfloat16* __restrict__ xh, const __nv_bfloat16* __restrict__ xl,
              const __nv_bfloat16* __restrict__ wqh, const __nv_bfloat16* __restrict__ wql,
              const __nv_bfloat16* __restrict__ wkh, const __nv_bfloat16* __restrict__ wkl,
              const __nv_bfloat16* __restrict__ wvh, const __nv_bfloat16* __restrict__ wvl,
              __nv_bfloat16* __restrict__ qh, __nv_bfloat16* __restrict__ ql,
              __nv_bfloat16* __restrict__ kh, __nv_bfloat16* __restrict__ kl,
              __nv_bfloat16* __restrict__ vh, __nv_bfloat16* __restrict__ vl,
              const float* __restrict__ fc, const float* __restrict__ fs)
{
    extern __shared__ char sm[];
    const uint32_t sbase = smem_u32(sm);
    const int bx   = blockIdx.x;
    const int brow = blockIdx.y * 128;

    const __nv_bfloat16 *Bh, *Bl;
    __nv_bfloat16 *Ch, *Cl;
    int N, bcol, mode;                      // mode: 1 rope+scale, 2 rope, 3 plain
    if (bx < 16)      { Bh = wqh; Bl = wql; Ch = qh; Cl = ql; N = DM;  bcol = bx * 128;        mode = 1; }
    else if (bx < 20) { Bh = wkh; Bl = wkl; Ch = kh; Cl = kl; N = KVD; bcol = (bx - 16) * 128; mode = 2; }
    else              { Bh = wvh; Bl = wvl; Ch = vh; Cl = vl; N = KVD; bcol = (bx - 20) * 128; mode = 3; }

    GemmAcc acc;
#pragma unroll
    for (int i = 0; i < 4; i++)
#pragma unroll
        for (int j = 0; j < 4; j++)
#pragma unroll
            for (int e = 0; e < 4; e++) acc.a[i][j][e] = 0.f;

    gemm_mainloop(xh, xl, Bh, Bl, brow, bcol, DM, sbase, sm, acc);

    const int warp = threadIdx.x >> 5;
    const int lane = threadIdx.x & 31;
    const int mrow0 = brow + (warp & 1) * 64 + (lane >> 2);
    const int ncol0 = bcol + (warp >> 1) * 32 + 2 * (lane & 3);
#pragma unroll
    for (int mt = 0; mt < 4; mt++) {
#pragma unroll
        for (int half = 0; half < 2; half++) {
            const int m = mrow0 + mt * 16 + half * 8;
#pragma unroll
            for (int nt = 0; nt < 4; nt++) {
                float v0 = acc.a[mt][nt][half * 2];
                float v1 = acc.a[mt][nt][half * 2 + 1];
                const int n = ncol0 + nt * 8;
                if (mode != 3) {
                    int p = (n & (HD - 1)) >> 1;
                    float cs = fc[m * (HD / 2) + p];
                    float sn = fs[m * (HD / 2) + p];
                    float a = v0, b = v1;
                    v0 = a * cs - b * sn;
                    v1 = a * sn + b * cs;
                    if (mode == 1) { v0 *= 0.125f; v1 *= 0.125f; }
                }
                uint32_t hp, lp;
                split2(v0, v1, hp, lp);
                *(uint32_t*)(Ch + (size_t)m * N + n) = hp;
                *(uint32_t*)(Cl + (size_t)m * N + n) = lp;
            }
        }
    }
}

// Output projection: fp32 result.
__global__ __launch_bounds__(256)
void out_gemm(const __nv_bfloat16* __restrict__ Ah, const __nv_bfloat16* __restrict__ Al,
              const __nv_bfloat16* __restrict__ Bh, const __nv_bfloat16* __restrict__ Bl,
              float* __restrict__ C)
{
    extern __shared__ char sm[];
    const uint32_t sbase = smem_u32(sm);
    const int brow = blockIdx.y * 128;
    const int bcol = blockIdx.x * 128;

    GemmAcc acc;
#pragma unroll
    for (int i = 0; i < 4; i++)
#pragma unroll
        for (int j = 0; j < 4; j++)
#pragma unroll
            for (int e = 0; e < 4; e++) acc.a[i][j][e] = 0.f;

    gemm_mainloop(Ah, Al, Bh, Bl, brow, bcol, DM, sbase, sm, acc);

    const int warp = threadIdx.x >> 5;
    const int lane = threadIdx.x & 31;
    const int mrow0 = brow + (warp & 1) * 64 + (lane >> 2);
    const int ncol0 = bcol + (warp >> 1) * 32 + 2 * (lane & 3);
#pragma unroll
    for (int mt = 0; mt < 4; mt++) {
#pragma unroll
        for (int half = 0; half < 2; half++) {
            const int m = mrow0 + mt * 16 + half * 8;
#pragma unroll
            for (int nt = 0; nt < 4; nt++) {
                const int n = ncol0 + nt * 8;
                *(float2*)(C + (size_t)m * DM + n) =
                    make_float2(acc.a[mt][nt][half * 2], acc.a[mt][nt][half * 2 + 1]);
            }
        }
    }
}

// ---------------- MMA flash attention: 128 queries/CTA, 8 warps ----------------
// smem: Q hi/lo 32KB + 2 stages x (Kh,Kl,Vh,Vl 8KB each) = 98304 B.
static constexpr int ATTN_SMEM = 32768 + 2 * 32768;

__global__ __launch_bounds__(256)
void attn_mma(const __nv_bfloat16* __restrict__ Qh, const __nv_bfloat16* __restrict__ Ql,
              const __nv_bfloat16* __restrict__ Kh, const __nv_bfloat16* __restrict__ Kl,
              const __nv_bfloat16* __restrict__ Vh, const __nv_bfloat16* __restrict__ Vl,
              __nv_bfloat16* __restrict__ Oh, __nv_bfloat16* __restrict__ Ol)
{
    extern __shared__ char sm[];
    const uint32_t sb = smem_u32(sm);
    const int tid  = threadIdx.x;
    const int warp = tid >> 5;
    const int lane = tid & 31;
    const int qt   = blockIdx.x;
    const int h    = blockIdx.y;
    const int kvh  = h >> 2;
    const int qb   = qt * 128;

    const uint32_t sQh = sb, sQl = sb + 16384;
    const uint32_t st0 = sb + 32768;

    const int kt0   = max(0, (qb - WIN) >> 6);
    const int ktmax = 2 * qt + 1;

    // Q tile: 128 rows x 128B, hi+lo
#pragma unroll
    for (int it = 0; it < 4; it++) {
        int idx = tid + it * 256;           // 0..1023
        int r = idx >> 3, c = idx & 7;
        uint32_t off = sw128((uint32_t)(r * 128 + c * 16));
        size_t go = (size_t)(qb + r) * DM + h * HD + c * 8;
        cp16(sQh + off, Qh + go);
        cp16(sQl + off, Ql + go);
    }
    auto load_kv = [&](uint32_t base, int kt) {
#pragma unroll
        for (int it = 0; it < 2; it++) {
            int idx = tid + it * 256;       // 0..511
            int r = idx >> 3, c = idx & 7;
            uint32_t off = sw128((uint32_t)(r * 128 + c * 16));
            size_t go = (size_t)(kt * 64 + r) * KVD + kvh * HD + c * 8;
            cp16(base + off,         Kh + go);
            cp16(base + 8192 + off,  Kl + go);
            cp16(base + 16384 + off, Vh + go);
            cp16(base + 24576 + off, Vl + go);
        }
    };
    load_kv(st0, kt0);
    cp_commit();
    cp_wait<0>();
    __syncthreads();

    uint32_t qfh[4][4], qfl[4][4];
    {
        const int a_r  = warp * 16 + (lane & 7) + 8 * ((lane >> 3) & 1);
        const int a_kb = 16 * (lane >> 4);
#pragma unroll
        for (int ks = 0; ks < 4; ks++) {
            uint32_t off = sw128((uint32_t)(a_r * 128 + ks * 32 + a_kb));
            ldsm_x4(qfh[ks], sQh + off);
            ldsm_x4(qfl[ks], sQl + off);
        }
    }

    float O[8][4];
#pragma unroll
    for (int nt = 0; nt < 8; nt++)
#pragma unroll
        for (int e = 0; e < 4; e++) O[nt][e] = 0.f;
    float m0 = -1e20f, m1 = -1e20f, l0 = 0.f, l1 = 0.f;

    const int i0 = qb + warp * 16 + (lane >> 2);
    const int i1 = i0 + 8;
    const int jc = 2 * (lane & 3);
    const int b_r  = lane & 7;
    const int b_kb = 16 * ((lane >> 3) & 1);
    const int v_r  = lane & 15;

    for (int kt = kt0; kt <= ktmax; kt++) {
        const int buf = (kt - kt0) & 1;
        if (kt < ktmax) { load_kv(st0 + (buf ^ 1) * 32768, kt + 1); cp_commit(); cp_wait<1>(); }
        else            { cp_wait<0>(); }
        __syncthreads();

        const uint32_t bK_h = st0 + buf * 32768;
        const uint32_t bK_l = bK_h + 8192;
        const uint32_t bV_h = bK_h + 16384;
        const uint32_t bV_l = bK_h + 24576;

        float S[8][4];
#pragma unroll
        for (int nt = 0; nt < 8; nt++) {
#pragma unroll
            for (int e = 0; e < 4; e++) S[nt][e] = 0.f;
#pragma unroll
            for (int ks = 0; ks < 4; ks++) {
                uint32_t boff = sw128((uint32_t)((nt * 8 + b_r) * 128 + ks * 32 + b_kb));
                uint32_t bh[2], bl[2];
                ldsm_x2(bh, bK_h + boff);
                ldsm_x2(bl, bK_l + boff);
                mma16816(S[nt], qfh[ks], bh);
                mma16816(S[nt], qfl[ks], bh);
                mma16816(S[nt], qfh[ks], bl);
            }
        }

        const int ktb = kt * 64;
        const bool full = (ktb >= qb + 127 - WIN) && (ktb + 64 <= qb);
        if (!full) {
#pragma unroll
            for (int nt = 0; nt < 8; nt++) {
                int j = ktb + nt * 8 + jc;
                if (j > i0 || j < i0 - WIN)         S[nt][0] = -1e30f;
                if (j + 1 > i0 || j + 1 < i0 - WIN) S[nt][1] = -1e30f;
                if (j > i1 || j < i1 - WIN)         S[nt][2] = -1e30f;
                if (j + 1 > i1 || j + 1 < i1 - WIN) S[nt][3] = -1e30f;
            }
        }

        float mx0 = -1e30f, mx1 = -1e30f;
#pragma unroll
        for (int nt = 0; nt < 8; nt++) {
            mx0 = fmaxf(mx0, fmaxf(S[nt][0], S[nt][1]));
            mx1 = fmaxf(mx1, fmaxf(S[nt][2], S[nt][3]));
        }
        mx0 = fmaxf(mx0, __shfl_xor_sync(0xffffffffu, mx0, 1));
        mx0 = fmaxf(mx0, __shfl_xor_sync(0xffffffffu, mx0, 2));
        mx1 = fmaxf(mx1, __shfl_xor_sync(0xffffffffu, mx1, 1));
        mx1 = fmaxf(mx1, __shfl_xor_sync(0xffffffffu, mx1, 2));
        const float mn0 = fmaxf(m0, mx0);
        const float mn1 = fmaxf(m1, mx1);
        const float sc0 = exp2f((m0 - mn0) * 1.44269504f);
        const float sc1 = exp2f((m1 - mn1) * 1.44269504f);
        m0 = mn0; m1 = mn1;
        l0 *= sc0; l1 *= sc1;
        float rs0 = 0.f, rs1 = 0.f;
#pragma unroll
        for (int nt = 0; nt < 8; nt++) {
            S[nt][0] = exp2f((S[nt][0] - mn0) * 1.44269504f);
            S[nt][1] = exp2f((S[nt][1] - mn0) * 1.44269504f);
            S[nt][2] = exp2f((S[nt][2] - mn1) * 1.44269504f);
            S[nt][3] = exp2f((S[nt][3] - mn1) * 1.44269504f);
            rs0 += S[nt][0] + S[nt][1];
            rs1 += S[nt][2] + S[nt][3];
            O[nt][0] *= sc0; O[nt][1] *= sc0;
            O[nt][2] *= sc1; O[nt][3] *= sc1;
        }
        rs0 += __shfl_xor_sync(0xffffffffu, rs0, 1);
        rs0 += __shfl_xor_sync(0xffffffffu, rs0, 2);
        rs1 += __shfl_xor_sync(0xffffffffu, rs1, 1);
        rs1 += __shfl_xor_sync(0xffffffffu, rs1, 2);
        l0 += rs0; l1 += rs1;

        uint32_t pah[4][4], pal[4][4];
#pragma unroll
        for (int ks = 0; ks < 4; ks++) {
            split2(S[2*ks][0],   S[2*ks][1],   pah[ks][0], pal[ks][0]);
            split2(S[2*ks][2],   S[2*ks][3],   pah[ks][1], pal[ks][1]);
            split2(S[2*ks+1][0], S[2*ks+1][1], pah[ks][2], pal[ks][2]);
            split2(S[2*ks+1][2], S[2*ks+1][3], pah[ks][3], pal[ks][3]);
        }

#pragma unroll
        for (int nt = 0; nt < 8; nt++) {
#pragma unroll
            for (int ks = 0; ks < 4; ks++) {
                uint32_t voff = sw128((uint32_t)((ks * 16 + v_r) * 128 + nt * 16));
                uint32_t vh[2], vl[2];
                ldsm_x2t(vh, bV_h + voff);
                ldsm_x2t(vl, bV_l + voff);
                mma16816(O[nt], pah[ks], vh);
                mma16816(O[nt], pah[ks], vl);
                mma16816(O[nt], pal[ks], vh);
            }
        }
        __syncthreads();
    }

    const float inv0 = 1.f / l0;
    const float inv1 = 1.f / l1;
    const int row0 = qb + warp * 16 + (lane >> 2);
    const int colb = h * HD + jc;
#pragma unroll
    for (int nt = 0; nt < 8; nt++) {
        uint32_t hp, lp;
        split2(O[nt][0] * inv0, O[nt][1] * inv0, hp, lp);
        size_t o = (size_t)row0 * DM + colb + nt * 8;
        *(uint32_t*)(Oh + o) = hp;
        *(uint32_t*)(Ol + o) = lp;
        split2(O[nt][2] * inv1, O[nt][3] * inv1, hp, lp);
        o += (size_t)8 * DM;
        *(uint32_t*)(Oh + o) = hp;
        *(uint32_t*)(Ol + o) = lp;
    }
}

// ---------------- launch --------------------------------------------------------
extern "C" void kernel_launch(void* const* d_in, const int* in_sizes, int n_in,
                              void* d_out, int out_size)
{
    const float* x  = (const float*)d_in[0];
    const float* wq = (const float*)d_in[1];
    const float* wk = (const float*)d_in[2];
    const float* wv = (const float*)d_in[3];
    const float* wo = (const float*)d_in[4];
    const float* fc = (const float*)d_in[5];
    const float* fs = (const float*)d_in[6];
    float* out = (float*)d_out;

    __nv_bfloat16 *xh, *xl, *wqh, *wql, *wkh, *wkl, *wvh, *wvl, *woh, *wol;
    __nv_bfloat16 *qh, *ql, *kh, *kl, *vh, *vl, *aoh, *aol;
    cudaGetSymbolAddress((void**)&xh,  g_xh);  cudaGetSymbolAddress((void**)&xl,  g_xl);
    cudaGetSymbolAddress((void**)&wqh, g_wqh); cudaGetSymbolAddress((void**)&wql, g_wql);
    cudaGetSymbolAddress((void**)&wkh, g_wkh); cudaGetSymbolAddress((void**)&wkl, g_wkl);
    cudaGetSymbolAddress((void**)&wvh, g_wvh); cudaGetSymbolAddress((void**)&wvl, g_wvl);
    cudaGetSymbolAddress((void**)&woh, g_woh); cudaGetSymbolAddress((void**)&wol, g_wol);
    cudaGetSymbolAddress((void**)&qh,  g_Qh);  cudaGetSymbolAddress((void**)&ql,  g_Ql);
    cudaGetSymbolAddress((void**)&kh,  g_Kh);  cudaGetSymbolAddress((void**)&kl,  g_Kl);
    cudaGetSymbolAddress((void**)&vh,  g_Vh);  cudaGetSymbolAddress((void**)&vl,  g_Vl);
    cudaGetSymbolAddress((void**)&aoh, g_aoh); cudaGetSymbolAddress((void**)&aol, g_aol);

    cudaFuncSetAttribute(qkv_gemm, cudaFuncAttributeMaxDynamicSharedMemorySize, GEMM_SMEM);
    cudaFuncSetAttribute(out_gemm, cudaFuncAttributeMaxDynamicSharedMemorySize, GEMM_SMEM);
    cudaFuncSetAttribute(attn_mma, cudaFuncAttributeMaxDynamicSharedMemorySize, ATTN_SMEM);

    const int n4 = SQ * DM / 4;
    split_kernel<<<n4 / 256, 256>>>(x, xh, xl, n4);
    transpose_split_all<<<5120, 256>>>(wq, wk, wv, wo,
                                       wqh, wql, wkh, wkl, wvh, wvl, woh, wol);

    qkv_gemm<<<dim3(24, 16), 256, GEMM_SMEM>>>(xh, xl, wqh, wql, wkh, wkl, wvh, wvl,
                                               qh, ql, kh, kl, vh, vl, fc, fs);

    attn_mma<<<dim3(SQ / 128, NH), 256, ATTN_SMEM>>>(qh, ql, kh, kl, vh, vl, aoh, aol);

    out_gemm<<<dim3(16, 16), 256, GEMM_SMEM>>>(aoh, aol, woh, wol, out);
}

// round 6
// speedup vs baseline: 4.8120x; 1.0174x over previous
#include <cuda_runtime.h>
#include <cuda_bf16.h>
#include <math.h>
#include <stdint.h>

#define SQ 2048
#define DM 2048
#define NH 32
#define NKV 8
#define HD 64
#define WIN 1024
#define KVD (NKV*HD)

// ---------------- scratch (device globals) -----------------------------------
__device__ __nv_bfloat16 g_xh [SQ*DM],  g_xl [SQ*DM];
__device__ __nv_bfloat16 g_wqh[DM*DM],  g_wql[DM*DM];    // [N][K]
__device__ __nv_bfloat16 g_wkh[KVD*DM], g_wkl[KVD*DM];
__device__ __nv_bfloat16 g_wvh[KVD*DM], g_wvl[KVD*DM];
__device__ __nv_bfloat16 g_woh[DM*DM],  g_wol[DM*DM];
__device__ __nv_bfloat16 g_Qh [SQ*DM],  g_Ql [SQ*DM];    // rope'd, scaled
__device__ __nv_bfloat16 g_Kh [SQ*KVD], g_Kl [SQ*KVD];   // rope'd
__device__ __nv_bfloat16 g_Vh [SQ*KVD], g_Vl [SQ*KVD];
__device__ __nv_bfloat16 g_aoh[SQ*DM],  g_aol[SQ*DM];

// ---------------- helpers -----------------------------------------------------
__device__ __forceinline__ uint32_t smem_u32(const void* p) {
    uint32_t a;
    asm("{ .reg .u64 t; cvta.to.shared.u64 t, %1; cvt.u32.u64 %0, t; }" : "=r"(a) : "l"(p));
    return a;
}
__device__ __forceinline__ uint32_t sw128(uint32_t o) { return o ^ ((o >> 3) & 0x70); }

__device__ __forceinline__ void cp16(uint32_t s, const void* g) {
    asm volatile("cp.async.cg.shared.global [%0], [%1], 16;" :: "r"(s), "l"(g));
}
__device__ __forceinline__ void cp_commit() { asm volatile("cp.async.commit_group;" ::: "memory"); }
template<int N> __device__ __forceinline__ void cp_wait() {
    asm volatile("cp.async.wait_group %0;" :: "n"(N) : "memory");
}

__device__ __forceinline__ void ldsm_x4(uint32_t* r, uint32_t addr) {
    asm volatile("ldmatrix.sync.aligned.m8n8.x4.shared.b16 {%0,%1,%2,%3}, [%4];"
                 : "=r"(r[0]), "=r"(r[1]), "=r"(r[2]), "=r"(r[3]) : "r"(addr));
}
__device__ __forceinline__ void ldsm_x4t(uint32_t* r, uint32_t addr) {
    asm volatile("ldmatrix.sync.aligned.m8n8.x4.trans.shared.b16 {%0,%1,%2,%3}, [%4];"
                 : "=r"(r[0]), "=r"(r[1]), "=r"(r[2]), "=r"(r[3]) : "r"(addr));
}
__device__ __forceinline__ void mma16816(float* c, const uint32_t* a, const uint32_t* b) {
    asm volatile("mma.sync.aligned.m16n8k16.row.col.f32.bf16.bf16.f32 "
                 "{%0,%1,%2,%3}, {%4,%5,%6,%7}, {%8,%9}, {%0,%1,%2,%3};"
                 : "+f"(c[0]), "+f"(c[1]), "+f"(c[2]), "+f"(c[3])
                 : "r"(a[0]), "r"(a[1]), "r"(a[2]), "r"(a[3]), "r"(b[0]), "r"(b[1]));
}
__device__ __forceinline__ uint32_t pack_bf16(float lo, float hi) {
    uint32_t r;
    asm("cvt.rn.bf16x2.f32 %0, %1, %2;" : "=r"(r) : "f"(hi), "f"(lo));
    return r;
}
__device__ __forceinline__ void split2(float v0, float v1, uint32_t& hp, uint32_t& lp) {
    hp = pack_bf16(v0, v1);
    float f0 = __uint_as_float(hp << 16);
    float f1 = __uint_as_float(hp & 0xffff0000u);
    lp = pack_bf16(v0 - f0, v1 - f1);
}

// ---------------- pre-pass: split x ------------------------------------------
__global__ void split_kernel(const float* __restrict__ X, __nv_bfloat16* __restrict__ H,
                             __nv_bfloat16* __restrict__ L, int n4)
{
    int i = blockIdx.x * blockDim.x + threadIdx.x;
    if (i >= n4) return;
    float4 v = ((const float4*)X)[i];
    uint32_t h0, l0, h1, l1;
    split2(v.x, v.y, h0, l0);
    split2(v.z, v.w, h1, l1);
    ((uint32_t*)H)[2*i] = h0; ((uint32_t*)H)[2*i+1] = h1;
    ((uint32_t*)L)[2*i] = l0; ((uint32_t*)L)[2*i+1] = l1;
}

// ---------------- pre-pass: all-weight transpose+split, one launch -------------
__device__ __forceinline__ void tsplit_tile(const float* __restrict__ W,
                                            __nv_bfloat16* __restrict__ Th,
                                            __nv_bfloat16* __restrict__ Tl,
                                            int K, int N, int tile, float (*t)[33])
{
    const int tid = threadIdx.x;
    const int ntn = N >> 5;
    const int k0 = (tile / ntn) << 6;
    const int n0 = (tile % ntn) << 5;
#pragma unroll
    for (int it = 0; it < 8; it++) {
        int idx = tid + it * 256;
        int r = idx >> 5, c = idx & 31;
        t[r][c] = W[(size_t)(k0 + r) * N + n0 + c];
    }
    __syncthreads();
    const int n  = tid >> 3;
    const int kk = tid & 7;
#pragma unroll
    for (int it = 0; it < 4; it++) {
        int kp = kk + it * 8;
        uint32_t hp, lp;
        split2(t[2*kp][n], t[2*kp+1][n], hp, lp);
        size_t o = (size_t)(n0 + n) * K + k0 + 2 * kp;
        *(uint32_t*)(Th + o) = hp;
        *(uint32_t*)(Tl + o) = lp;
    }
    __syncthreads();
}

__global__ __launch_bounds__(256)
void transpose_split_all(const float* __restrict__ wq, const float* __restrict__ wk,
                         const float* __restrict__ wv, const float* __restrict__ wo,
                         __nv_bfloat16* wqh, __nv_bfloat16* wql,
                         __nv_bfloat16* wkh, __nv_bfloat16* wkl,
                         __nv_bfloat16* wvh, __nv_bfloat16* wvl,
                         __nv_bfloat16* woh, __nv_bfloat16* wol)
{
    __shared__ float t[64][33];
    int b = blockIdx.x;
    if (b < 2048)        tsplit_tile(wq, wqh, wql, DM, DM,  b,        t);
    else if (b < 2560)   tsplit_tile(wk, wkh, wkl, DM, KVD, b - 2048, t);
    else if (b < 3072)   tsplit_tile(wv, wvh, wvl, DM, KVD, b - 2560, t);
    else                 tsplit_tile(wo, woh, wol, DM, DM,  b - 3072, t);
}

// ---------------- GEMM core: 3-stage cp.async, 128x128 tile, BK=64 -------------
static constexpr int GEMM_SMEM = 3 * 65536;

struct GemmAcc { float a[4][4][4]; };

__device__ __forceinline__ void gemm_mainloop(
    const __nv_bfloat16* __restrict__ Ah, const __nv_bfloat16* __restrict__ Al,
    const __nv_bfloat16* __restrict__ Bh, const __nv_bfloat16* __restrict__ Bl,
    int brow, int bcol, int K, uint32_t sbase, GemmAcc& acc)
{
    const int tid  = threadIdx.x;
    const int warp = tid >> 5;
    const int lane = tid & 31;
    const int wm   = (warp & 1) * 64;
    const int wn   = (warp >> 1) * 32;

    const int a_r   = (lane & 7) + 8 * ((lane >> 3) & 1);
    const int a_kb  = 16 * (lane >> 4);
    const int bx_r  = lane & 7;
    const int bx_nt = lane >> 4;             // 0/1 -> +nt
    const int bx_kb = 16 * ((lane >> 3) & 1);

    auto load_stage = [&](int s, int k0) {
        uint32_t base = sbase + s * 65536;
#pragma unroll
        for (int it = 0; it < 4; it++) {
            int idx = tid + it * 256;
            int r   = idx >> 3;
            int c   = idx & 7;
            uint32_t off = sw128((uint32_t)(r * 128 + c * 16));
            cp16(base + off,         Ah + (size_t)(brow + r) * K + k0 + c * 8);
            cp16(base + 16384 + off, Al + (size_t)(brow + r) * K + k0 + c * 8);
            cp16(base + 32768 + off, Bh + (size_t)(bcol + r) * K + k0 + c * 8);
            cp16(base + 49152 + off, Bl + (size_t)(bcol + r) * K + k0 + c * 8);
        }
    };

    const int nch = K >> 6;
    load_stage(0, 0);  cp_commit();
    load_stage(1, 64); cp_commit();

    int s = 0;
    for (int c = 0; c < nch; c++) {
        if (c + 2 < nch) load_stage((s + 2 >= 3) ? s - 1 : s + 2, (c + 2) << 6);
        cp_commit();
        cp_wait<2>();
        __syncthreads();

        uint32_t base = sbase + s * 65536;
#pragma unroll
        for (int ks = 0; ks < 4; ks++) {
            const int kb = ks * 32;
            uint32_t bh[4][2], bl[4][2];
#pragma unroll
            for (int ntp = 0; ntp < 2; ntp++) {
                uint32_t off = sw128((uint32_t)((wn + (2*ntp + bx_nt) * 8 + bx_r) * 128 + kb + bx_kb));
                uint32_t r[4];
                ldsm_x4(r, base + 32768 + off);
                bh[2*ntp][0] = r[0]; bh[2*ntp][1] = r[1];
                bh[2*ntp+1][0] = r[2]; bh[2*ntp+1][1] = r[3];
                ldsm_x4(r, base + 49152 + off);
                bl[2*ntp][0] = r[0]; bl[2*ntp][1] = r[1];
                bl[2*ntp+1][0] = r[2]; bl[2*ntp+1][1] = r[3];
            }
            uint32_t ah[2][4], al[2][4];
            {
                uint32_t aoff = sw128((uint32_t)((wm + a_r) * 128 + kb + a_kb));
                ldsm_x4(ah[0], base + aoff);
                ldsm_x4(al[0], base + 16384 + aoff);
            }
#pragma unroll
            for (int mt = 0; mt < 4; mt++) {
                const int cur = mt & 1, nxt = cur ^ 1;
                if (mt < 3) {
                    uint32_t aoff = sw128((uint32_t)((wm + (mt+1) * 16 + a_r) * 128 + kb + a_kb));
                    ldsm_x4(ah[nxt], base + aoff);
                    ldsm_x4(al[nxt], base + 16384 + aoff);
                }
                // term-major: same-acc MMAs are 4 issues apart
#pragma unroll
                for (int nt = 0; nt < 4; nt++) mma16816(acc.a[mt][nt], ah[cur], bh[nt]);
#pragma unroll
                for (int nt = 0; nt < 4; nt++) mma16816(acc.a[mt][nt], al[cur], bh[nt]);
#pragma unroll
                for (int nt = 0; nt < 4; nt++) mma16816(acc.a[mt][nt], ah[cur], bl[nt]);
            }
        }
        __syncthreads();
        s = (s + 1 >= 3) ? 0 : s + 1;
    }
}

// Fused QKV projection: grid.x = 24 (0-15 Q | 16-19 K | 20-23 V), grid.y = 16.
__global__ __launch_bounds__(256, 2)
void qkv_gemm(const __nv_bfloat16* __restrict__ xh, const __nv_bfloat16* __restrict__ xl,
              const __nv_bfloat16* __restrict__ wqh, const __nv_bfloat16* __restrict__ wql,
              const __nv_bfloat16* __restrict__ wkh, const __nv_bfloat16* __restrict__ wkl,
              const __nv_bfloat16* __restrict__ wvh, const __nv_bfloat16* __restrict__ wvl,
              __nv_bfloat16* __restrict__ qh, __nv_bfloat16* __restrict__ ql,
              __nv_bfloat16* __restrict__ kh, __nv_bfloat16* __restrict__ kl,
              __nv_bfloat16* __restrict__ vh, __nv_bfloat16* __restrict__ vl,
              const float* __restrict__ fc, const float* __restrict__ fs)
{
    extern __shared__ char sm[];
    const uint32_t sbase = smem_u32(sm);
    const int bx   = blockIdx.x;
    const int brow = blockIdx.y * 128;

    const __nv_bfloat16 *Bh, *Bl;
    __nv_bfloat16 *Ch, *Cl;
    int N, bcol, mode;
    if (bx < 16)      { Bh = wqh; Bl = wql; Ch = qh; Cl = ql; N = DM;  bcol = bx * 128;        mode = 1; }
    else if (bx < 20) { Bh = wkh; Bl = wkl; Ch = kh; Cl = kl; N = KVD; bcol = (bx - 16) * 128; mode = 2; }
    else              { Bh = wvh; Bl = wvl; Ch = vh; Cl = vl; N = KVD; bcol = (bx - 20) * 128; mode = 3; }

    GemmAcc acc;
#pragma unroll
    for (int i = 0; i < 4; i++)
#pragma unroll
        for (int j = 0; j < 4; j++)
#pragma unroll
            for (int e = 0; e < 4; e++) acc.a[i][j][e] = 0.f;

    gemm_mainloop(xh, xl, Bh, Bl, brow, bcol, DM, sbase, acc);

    const int warp = threadIdx.x >> 5;
    const int lane = threadIdx.x & 31;
    const int mrow0 = brow + (warp & 1) * 64 + (lane >> 2);
    const int ncol0 = bcol + (warp >> 1) * 32 + 2 * (lane & 3);
#pragma unroll
    for (int mt = 0; mt < 4; mt++) {
#pragma unroll
        for (int half = 0; half < 2; half++) {
            const int m = mrow0 + mt * 16 + half * 8;
#pragma unroll
            for (int nt = 0; nt < 4; nt++) {
                float v0 = acc.a[mt][nt][half * 2];
                float v1 = acc.a[mt][nt][half * 2 + 1];
                const int n = ncol0 + nt * 8;
                if (mode != 3) {
                    int p = (n & (HD - 1)) >> 1;
                    float cs = fc[m * (HD / 2) + p];
                    float sn = fs[m * (HD / 2) + p];
                    float a = v0, b = v1;
                    v0 = a * cs - b * sn;
                    v1 = a * sn + b * cs;
                    if (mode == 1) { v0 *= 0.125f; v1 *= 0.125f; }
                }
                uint32_t hp, lp;
                split2(v0, v1, hp, lp);
                *(uint32_t*)(Ch + (size_t)m * N + n) = hp;
                *(uint32_t*)(Cl + (size_t)m * N + n) = lp;
            }
        }
    }
}

__global__ __launch_bounds__(256, 2)
void out_gemm(const __nv_bfloat16* __restrict__ Ah, const __nv_bfloat16* __restrict__ Al,
              const __nv_bfloat16* __restrict__ Bh, const __nv_bfloat16* __restrict__ Bl,
              float* __restrict__ C)
{
    extern __shared__ char sm[];
    const uint32_t sbase = smem_u32(sm);
    const int brow = blockIdx.y * 128;
    const int bcol = blockIdx.x * 128;

    GemmAcc acc;
#pragma unroll
    for (int i = 0; i < 4; i++)
#pragma unroll
        for (int j = 0; j < 4; j++)
#pragma unroll
            for (int e = 0; e < 4; e++) acc.a[i][j][e] = 0.f;

    gemm_mainloop(Ah, Al, Bh, Bl, brow, bcol, DM, sbase, acc);

    const int warp = threadIdx.x >> 5;
    const int lane = threadIdx.x & 31;
    const int mrow0 = brow + (warp & 1) * 64 + (lane >> 2);
    const int ncol0 = bcol + (warp >> 1) * 32 + 2 * (lane & 3);
#pragma unroll
    for (int mt = 0; mt < 4; mt++) {
#pragma unroll
        for (int half = 0; half < 2; half++) {
            const int m = mrow0 + mt * 16 + half * 8;
#pragma unroll
            for (int nt = 0; nt < 4; nt++) {
                const int n = ncol0 + nt * 8;
                *(float2*)(C + (size_t)m * DM + n) =
                    make_float2(acc.a[mt][nt][half * 2], acc.a[mt][nt][half * 2 + 1]);
            }
        }
    }
}

// ---------------- MMA flash attention: 128 queries/CTA, 8 warps ----------------
static constexpr int ATTN_SMEM = 32768 + 2 * 32768;

__global__ __launch_bounds__(256, 2)
void attn_mma(const __nv_bfloat16* __restrict__ Qh, const __nv_bfloat16* __restrict__ Ql,
              const __nv_bfloat16* __restrict__ Kh, const __nv_bfloat16* __restrict__ Kl,
              const __nv_bfloat16* __restrict__ Vh, const __nv_bfloat16* __restrict__ Vl,
              __nv_bfloat16* __restrict__ Oh, __nv_bfloat16* __restrict__ Ol)
{
    extern __shared__ char sm[];
    const uint32_t sb = smem_u32(sm);
    const int tid  = threadIdx.x;
    const int warp = tid >> 5;
    const int lane = tid & 31;
    const int qt   = blockIdx.x;
    const int h    = blockIdx.y;
    const int kvh  = h >> 2;
    const int qb   = qt * 128;

    const uint32_t sQh = sb, sQl = sb + 16384;
    const uint32_t st0 = sb + 32768;

    const int kt0   = max(0, (qb - WIN) >> 6);
    const int ktmax = 2 * qt + 1;

#pragma unroll
    for (int it = 0; it < 4; it++) {
        int idx = tid + it * 256;
        int r = idx >> 3, c = idx & 7;
        uint32_t off = sw128((uint32_t)(r * 128 + c * 16));
        size_t go = (size_t)(qb + r) * DM + h * HD + c * 8;
        cp16(sQh + off, Qh + go);
        cp16(sQl + off, Ql + go);
    }
    auto load_kv = [&](uint32_t base, int kt) {
#pragma unroll
        for (int it = 0; it < 2; it++) {
            int idx = tid + it * 256;
            int r = idx >> 3, c = idx & 7;
            uint32_t off = sw128((uint32_t)(r * 128 + c * 16));
            size_t go = (size_t)(kt * 64 + r) * KVD + kvh * HD + c * 8;
            cp16(base + off,         Kh + go);
            cp16(base + 8192 + off,  Kl + go);
            cp16(base + 16384 + off, Vh + go);
            cp16(base + 24576 + off, Vl + go);
        }
    };
    load_kv(st0, kt0);
    cp_commit();
    cp_wait<0>();
    __syncthreads();

    uint32_t qfh[4][4], qfl[4][4];
    {
        const int a_r  = warp * 16 + (lane & 7) + 8 * ((lane >> 3) & 1);
        const int a_kb = 16 * (lane >> 4);
#pragma unroll
        for (int ks = 0; ks < 4; ks++) {
            uint32_t off = sw128((uint32_t)(a_r * 128 + ks * 32 + a_kb));
            ldsm_x4(qfh[ks], sQh + off);
            ldsm_x4(qfl[ks], sQl + off);
        }
    }

    float O[8][4];
#pragma unroll
    for (int nt = 0; nt < 8; nt++)
#pragma unroll
        for (int e = 0; e < 4; e++) O[nt][e] = 0.f;
    float m0 = -1e20f, m1 = -1e20f, l0 = 0.f, l1 = 0.f;

    const int i0 = qb + warp * 16 + (lane >> 2);
    const int i1 = i0 + 8;
    const int jc = 2 * (lane & 3);
    const int wrow0 = qb + warp * 16;         // warp min row
    // x4 lane mappings
    const int kx_r  = lane & 7;
    const int kx_nt = lane >> 4;
    const int kx_kb = 16 * ((lane >> 3) & 1);
    const int vx_r  = lane & 15;
    const int vx_nt = lane >> 4;

    for (int kt = kt0; kt <= ktmax; kt++) {
        const int buf = (kt - kt0) & 1;
        if (kt < ktmax) { load_kv(st0 + (buf ^ 1) * 32768, kt + 1); cp_commit(); cp_wait<1>(); }
        else            { cp_wait<0>(); }
        __syncthreads();

        const int ktb = kt * 64;
        // per-warp window skip: any (i in warp rows, j in tile) with j<=i && j>=i-WIN?
        const bool act = (ktb <= wrow0 + 15) && (ktb + 63 >= wrow0 - WIN);
        if (act) {
            const uint32_t bK_h = st0 + buf * 32768;
            const uint32_t bK_l = bK_h + 8192;
            const uint32_t bV_h = bK_h + 16384;
            const uint32_t bV_l = bK_h + 24576;

            float S[8][4];
#pragma unroll
            for (int nt = 0; nt < 8; nt++)
#pragma unroll
                for (int e = 0; e < 4; e++) S[nt][e] = 0.f;

#pragma unroll
            for (int ks = 0; ks < 4; ks++) {
                const int kb = ks * 32;
                uint32_t kf[8][2];
#pragma unroll
                for (int ntp = 0; ntp < 4; ntp++) {
                    uint32_t off = sw128((uint32_t)(((2*ntp + kx_nt) * 8 + kx_r) * 128 + kb + kx_kb));
                    uint32_t r[4];
                    ldsm_x4(r, bK_h + off);
                    kf[2*ntp][0] = r[0]; kf[2*ntp][1] = r[1];
                    kf[2*ntp+1][0] = r[2]; kf[2*ntp+1][1] = r[3];
                }
#pragma unroll
                for (int nt = 0; nt < 8; nt++) mma16816(S[nt], qfh[ks], kf[nt]);
#pragma unroll
                for (int nt = 0; nt < 8; nt++) mma16816(S[nt], qfl[ks], kf[nt]);
#pragma unroll
                for (int ntp = 0; ntp < 4; ntp++) {
                    uint32_t off = sw128((uint32_t)(((2*ntp + kx_nt) * 8 + kx_r) * 128 + kb + kx_kb));
                    uint32_t r[4];
                    ldsm_x4(r, bK_l + off);
                    kf[2*ntp][0] = r[0]; kf[2*ntp][1] = r[1];
                    kf[2*ntp+1][0] = r[2]; kf[2*ntp+1][1] = r[3];
                }
#pragma unroll
                for (int nt = 0; nt < 8; nt++) mma16816(S[nt], qfh[ks], kf[nt]);
            }

            const bool full = (ktb >= qb + 127 - WIN) && (ktb + 64 <= qb);
            if (!full) {
#pragma unroll
                for (int nt = 0; nt < 8; nt++) {
                    int j = ktb + nt * 8 + jc;
                    if (j > i0 || j < i0 - WIN)         S[nt][0] = -1e30f;
                    if (j + 1 > i0 || j + 1 < i0 - WIN) S[nt][1] = -1e30f;
                    if (j > i1 || j < i1 - WIN)         S[nt][2] = -1e30f;
                    if (j + 1 > i1 || j + 1 < i1 - WIN) S[nt][3] = -1e30f;
                }
            }

            float mx0 = -1e30f, mx1 = -1e30f;
#pragma unroll
            for (int nt = 0; nt < 8; nt++) {
                mx0 = fmaxf(mx0, fmaxf(S[nt][0], S[nt][1]));
                mx1 = fmaxf(mx1, fmaxf(S[nt][2], S[nt][3]));
            }
            mx0 = fmaxf(mx0, __shfl_xor_sync(0xffffffffu, mx0, 1));
            mx0 = fmaxf(mx0, __shfl_xor_sync(0xffffffffu, mx0, 2));
            mx1 = fmaxf(mx1, __shfl_xor_sync(0xffffffffu, mx1, 1));
            mx1 = fmaxf(mx1, __shfl_xor_sync(0xffffffffu, mx1, 2));
            const float mn0 = fmaxf(m0, mx0);
            const float mn1 = fmaxf(m1, mx1);
            const float sc0 = exp2f((m0 - mn0) * 1.44269504f);
            const float sc1 = exp2f((m1 - mn1) * 1.44269504f);
            m0 = mn0; m1 = mn1;
            l0 *= sc0; l1 *= sc1;
            float rs0 = 0.f, rs1 = 0.f;
#pragma unroll
            for (int nt = 0; nt < 8; nt++) {
                S[nt][0] = exp2f((S[nt][0] - mn0) * 1.44269504f);
                S[nt][1] = exp2f((S[nt][1] - mn0) * 1.44269504f);
                S[nt][2] = exp2f((S[nt][2] - mn1) * 1.44269504f);
                S[nt][3] = exp2f((S[nt][3] - mn1) * 1.44269504f);
                rs0 += S[nt][0] + S[nt][1];
                rs1 += S[nt][2] + S[nt][3];
                O[nt][0] *= sc0; O[nt][1] *= sc0;
                O[nt][2] *= sc1; O[nt][3] *= sc1;
            }
            rs0 += __shfl_xor_sync(0xffffffffu, rs0, 1);
            rs0 += __shfl_xor_sync(0xffffffffu, rs0, 2);
            rs1 += __shfl_xor_sync(0xffffffffu, rs1, 1);
            rs1 += __shfl_xor_sync(0xffffffffu, rs1, 2);
            l0 += rs0; l1 += rs1;

            uint32_t pah[4][4], pal[4][4];
#pragma unroll
            for (int ks = 0; ks < 4; ks++) {
                split2(S[2*ks][0],   S[2*ks][1],   pah[ks][0], pal[ks][0]);
                split2(S[2*ks][2],   S[2*ks][3],   pah[ks][1], pal[ks][1]);
                split2(S[2*ks+1][0], S[2*ks+1][1], pah[ks][2], pal[ks][2]);
                split2(S[2*ks+1][2], S[2*ks+1][3], pah[ks][3], pal[ks][3]);
            }

#pragma unroll
            for (int ks = 0; ks < 4; ks++) {
                uint32_t vf[8][2];
#pragma unroll
                for (int ntp = 0; ntp < 4; ntp++) {
                    uint32_t off = sw128((uint32_t)((ks * 16 + vx_r) * 128 + (2*ntp + vx_nt) * 16));
                    uint32_t r[4];
                    ldsm_x4t(r, bV_h + off);
                    vf[2*ntp][0] = r[0]; vf[2*ntp][1] = r[1];
                    vf[2*ntp+1][0] = r[2]; vf[2*ntp+1][1] = r[3];
                }
#pragma unroll
                for (int nt = 0; nt < 8; nt++) mma16816(O[nt], pah[ks], vf[nt]);
#pragma unroll
                for (int nt = 0; nt < 8; nt++) mma16816(O[nt], pal[ks], vf[nt]);
#pragma unroll
                for (int ntp = 0; ntp < 4; ntp++) {
                    uint32_t off = sw128((uint32_t)((ks * 16 + vx_r) * 128 + (2*ntp + vx_nt) * 16));
                    uint32_t r[4];
                    ldsm_x4t(r, bV_l + off);
                    vf[2*ntp][0] = r[0]; vf[2*ntp][1] = r[1];
                    vf[2*ntp+1][0] = r[2]; vf[2*ntp+1][1] = r[3];
                }
#pragma unroll
                for (int nt = 0; nt < 8; nt++) mma16816(O[nt], pah[ks], vf[nt]);
            }
        }
        __syncthreads();
    }

    const float inv0 = 1.f / l0;
    const float inv1 = 1.f / l1;
    const int row0 = qb + warp * 16 + (lane >> 2);
    const int colb = h * HD + jc;
#pragma unroll
    for (int nt = 0; nt < 8; nt++) {
        uint32_t hp, lp;
        split2(O[nt][0] * inv0, O[nt][1] * inv0, hp, lp);
        size_t o = (size_t)row0 * DM + colb + nt * 8;
        *(uint32_t*)(Oh + o) = hp;
        *(uint32_t*)(Ol + o) = lp;
        split2(O[nt][2] * inv1, O[nt][3] * inv1, hp, lp);
        o += (size_t)8 * DM;
        *(uint32_t*)(Oh + o) = hp;
        *(uint32_t*)(Ol + o) = lp;
    }
}

// ---------------- launch --------------------------------------------------------
extern "C" void kernel_launch(void* const* d_in, const int* in_sizes, int n_in,
                              void* d_out, int out_size)
{
    const float* x  = (const float*)d_in[0];
    const float* wq = (const float*)d_in[1];
    const float* wk = (const float*)d_in[2];
    const float* wv = (const float*)d_in[3];
    const float* wo = (const float*)d_in[4];
    const float* fc = (const float*)d_in[5];
    const float* fs = (const float*)d_in[6];
    float* out = (float*)d_out;

    __nv_bfloat16 *xh, *xl, *wqh, *wql, *wkh, *wkl, *wvh, *wvl, *woh, *wol;
    __nv_bfloat16 *qh, *ql, *kh, *kl, *vh, *vl, *aoh, *aol;
    cudaGetSymbolAddress((void**)&xh,  g_xh);  cudaGetSymbolAddress((void**)&xl,  g_xl);
    cudaGetSymbolAddress((void**)&wqh, g_wqh); cudaGetSymbolAddress((void**)&wql, g_wql);
    cudaGetSymbolAddress((void**)&wkh, g_wkh); cudaGetSymbolAddress((void**)&wkl, g_wkl);
    cudaGetSymbolAddress((void**)&wvh, g_wvh); cudaGetSymbolAddress((void**)&wvl, g_wvl);
    cudaGetSymbolAddress((void**)&woh, g_woh); cudaGetSymbolAddress((void**)&wol, g_wol);
    cudaGetSymbolAddress((void**)&qh,  g_Qh);  cudaGetSymbolAddress((void**)&ql,  g_Ql);
    cudaGetSymbolAddress((void**)&kh,  g_Kh);  cudaGetSymbolAddress((void**)&kl,  g_Kl);
    cudaGetSymbolAddress((void**)&vh,  g_Vh);  cudaGetSymbolAddress((void**)&vl,  g_Vl);
    cudaGetSymbolAddress((void**)&aoh, g_aoh); cudaGetSymbolAddress((void**)&aol, g_aol);

    cudaFuncSetAttribute(qkv_gemm, cudaFuncAttributeMaxDynamicSharedMemorySize, GEMM_SMEM);
    cudaFuncSetAttribute(out_gemm, cudaFuncAttributeMaxDynamicSharedMemorySize, GEMM_SMEM);
    cudaFuncSetAttribute(attn_mma, cudaFuncAttributeMaxDynamicSharedMemorySize, ATTN_SMEM);

    const int n4 = SQ * DM / 4;
    split_kernel<<<n4 / 256, 256>>>(x, xh, xl, n4);
    transpose_split_all<<<5120, 256>>>(wq, wk, wv, wo,
                                       wqh, wql, wkh, wkl, wvh, wvl, woh, wol);

    qkv_gemm<<<dim3(24, 16), 256, GEMM_SMEM>>>(xh, xl, wqh, wql, wkh, wkl, wvh, wvl,
                                               qh, ql, kh, kl, vh, vl, fc, fs);

    attn_mma<<<dim3(SQ / 128, NH), 256, ATTN_SMEM>>>(qh, ql, kh, kl, vh, vl, aoh, aol);

    out_gemm<<<dim3(16, 16), 256, GEMM_SMEM>>>(aoh, aol, woh, wol, out);
}